// round 1
// baseline (speedup 1.0000x reference)
#include <cuda_runtime.h>
#include <math.h>

// Problem constants
#define Bb 4
#define Ss 1024
#define Ee 1024
#define Hh 16
#define DH 64
#define MROWS (Bb * Ss)      // 4096
#define QKVN (3 * Ee)        // 3072

// Scratch (device globals are the allowed scratch mechanism)
__device__ float g_qkv[(size_t)MROWS * QKVN];         // 50.3 MB
__device__ float g_P[(size_t)Bb * Hh * Ss * Ss];      // 268 MB (logits/probs/filtered)
__device__ float g_ao[(size_t)MROWS * Ee];            // 16.8 MB (attn output, [b,s,h,d])
__device__ float g_spill[(size_t)MROWS * Ee];         // fallback main-out if not in d_out

// ---------------------------------------------------------------------------
// Generic SGEMM: C[M,N] = A[M,K] @ B[K,N] (+ bias[N]).  BM=BN=128, BK=16,
// TM=TN=8, 256 threads. M%128==0, N%128==0, K%16==0 assumed (true here).
// ---------------------------------------------------------------------------
__global__ __launch_bounds__(256) void sgemm_bias_kernel(
    const float* __restrict__ A, const float* __restrict__ Bm,
    const float* __restrict__ bias, float* __restrict__ C,
    int Mdim, int Ndim, int Kdim)
{
    constexpr int BM = 128, BN = 128, BK = 16, TM = 8, TN = 8;
    __shared__ float As[BK][BM];
    __shared__ float Bs[BK][BN];

    const int tid = threadIdx.x;
    const int cRow = blockIdx.y, cCol = blockIdx.x;
    const int threadRow = tid / (BN / TN);   // 0..15
    const int threadCol = tid % (BN / TN);   // 0..15

    const float* Ab = A + (size_t)cRow * BM * Kdim;
    const float* Bbp = Bm + (size_t)cCol * BN;

    float acc[TM][TN] = {};
    float regM[TM], regN[TN];

    const int aRow = tid / (BK / 4);          // 0..63
    const int aCol = (tid % (BK / 4)) * 4;    // 0,4,8,12
    const int bRow = tid / (BN / 4);          // 0..7
    const int bCol = (tid % (BN / 4)) * 4;    // 0..124

    for (int k0 = 0; k0 < Kdim; k0 += BK) {
        #pragma unroll
        for (int r = 0; r < BM; r += 64) {
            float4 v = *(const float4*)(Ab + (size_t)(aRow + r) * Kdim + k0 + aCol);
            As[aCol + 0][aRow + r] = v.x;
            As[aCol + 1][aRow + r] = v.y;
            As[aCol + 2][aRow + r] = v.z;
            As[aCol + 3][aRow + r] = v.w;
        }
        #pragma unroll
        for (int r = 0; r < BK; r += 8) {
            float4 v = *(const float4*)(Bbp + (size_t)(k0 + bRow + r) * Ndim + bCol);
            *(float4*)(&Bs[bRow + r][bCol]) = v;
        }
        __syncthreads();

        #pragma unroll
        for (int k = 0; k < BK; ++k) {
            #pragma unroll
            for (int i = 0; i < TM; ++i) regM[i] = As[k][threadRow * TM + i];
            #pragma unroll
            for (int j = 0; j < TN; ++j) regN[j] = Bs[k][threadCol * TN + j];
            #pragma unroll
            for (int i = 0; i < TM; ++i)
                #pragma unroll
                for (int j = 0; j < TN; ++j)
                    acc[i][j] += regM[i] * regN[j];
        }
        __syncthreads();
    }

    #pragma unroll
    for (int i = 0; i < TM; ++i) {
        const int row = cRow * BM + threadRow * TM + i;
        #pragma unroll
        for (int j = 0; j < TN; j += 4) {
            const int col = cCol * BN + threadCol * TN + j;
            float4 v;
            v.x = acc[i][j + 0] + (bias ? bias[col + 0] : 0.f);
            v.y = acc[i][j + 1] + (bias ? bias[col + 1] : 0.f);
            v.z = acc[i][j + 2] + (bias ? bias[col + 2] : 0.f);
            v.w = acc[i][j + 3] + (bias ? bias[col + 3] : 0.f);
            *(float4*)(C + (size_t)row * Ndim + col) = v;
        }
    }
}

// ---------------------------------------------------------------------------
// QK^T logits: P[bh, i, j] = scale * dot(Q[bh,i,:], K[bh,j,:]), Dh=64.
// grid (S/64, S/64, B*H), 64x64 tile per block, 256 threads (4x4 each).
// ---------------------------------------------------------------------------
__global__ __launch_bounds__(256) void qk_logits_kernel(
    const float* __restrict__ qkv, float* __restrict__ P)
{
    const int bh = blockIdx.z;
    const int b = bh / Hh, h = bh % Hh;
    const int i0 = blockIdx.y * 64, j0 = blockIdx.x * 64;

    const float* Qb = qkv + (size_t)(b * Ss) * QKVN + h * DH;        // stride QKVN
    const float* Kb = qkv + (size_t)(b * Ss) * QKVN + Ee + h * DH;   // stride QKVN

    __shared__ float Qs[DH][64 + 1];   // [k][i]
    __shared__ float Ks[DH][64 + 1];   // [k][j]

    const int tid = threadIdx.x;
    const int lr = tid / 16;             // 0..15
    const int lc = (tid % 16) * 4;       // 0..60

    #pragma unroll
    for (int r = 0; r < 64; r += 16) {
        float4 q = *(const float4*)(Qb + (size_t)(i0 + lr + r) * QKVN + lc);
        Qs[lc + 0][lr + r] = q.x; Qs[lc + 1][lr + r] = q.y;
        Qs[lc + 2][lr + r] = q.z; Qs[lc + 3][lr + r] = q.w;
        float4 kk = *(const float4*)(Kb + (size_t)(j0 + lr + r) * QKVN + lc);
        Ks[lc + 0][lr + r] = kk.x; Ks[lc + 1][lr + r] = kk.y;
        Ks[lc + 2][lr + r] = kk.z; Ks[lc + 3][lr + r] = kk.w;
    }
    __syncthreads();

    const int ti = (tid / 16) * 4;
    const int tj = (tid % 16) * 4;
    float acc[4][4] = {};

    #pragma unroll
    for (int k = 0; k < DH; ++k) {
        float rm[4], rn[4];
        #pragma unroll
        for (int i = 0; i < 4; ++i) rm[i] = Qs[k][ti + i];
        #pragma unroll
        for (int j = 0; j < 4; ++j) rn[j] = Ks[k][tj + j];
        #pragma unroll
        for (int i = 0; i < 4; ++i)
            #pragma unroll
            for (int j = 0; j < 4; ++j)
                acc[i][j] += rm[i] * rn[j];
    }

    const float scale = 0.125f;   // 64^-0.5
    float* Pr = P + ((size_t)bh * Ss + i0) * Ss + j0;
    #pragma unroll
    for (int i = 0; i < 4; ++i) {
        float4 v;
        v.x = acc[i][0] * scale; v.y = acc[i][1] * scale;
        v.z = acc[i][2] * scale; v.w = acc[i][3] * scale;
        *(float4*)(Pr + (size_t)(ti + i) * Ss + tj) = v;
    }
}

// ---------------------------------------------------------------------------
// Fused softmax + threshold mask + renormalize, in place on P.
// filtered[i,j] = (p>thr) ? p / sum(p where p>thr) : 0 ; if none pass: one-hot
// at argmax. One block per row (1024 cols), 256 threads.
// ---------------------------------------------------------------------------
__global__ __launch_bounds__(256) void softmax_mask_kernel(float* __restrict__ P)
{
    const size_t row = blockIdx.x;
    float* Pr = P + row * (size_t)Ss;
    const int tid = threadIdx.x;

    float l[4];
    #pragma unroll
    for (int r = 0; r < 4; ++r) l[r] = Pr[tid + 256 * r];

    // per-thread max + argmax (first occurrence)
    float m = l[0]; int mi = tid;
    #pragma unroll
    for (int r = 1; r < 4; ++r) {
        if (l[r] > m) { m = l[r]; mi = tid + 256 * r; }
    }

    __shared__ float sval[256];
    __shared__ int   sidx[256];
    __shared__ float sred[256];

    sval[tid] = m; sidx[tid] = mi;
    __syncthreads();
    for (int s = 128; s > 0; s >>= 1) {
        if (tid < s) {
            float o = sval[tid + s]; int oi = sidx[tid + s];
            if (o > sval[tid] || (o == sval[tid] && oi < sidx[tid])) {
                sval[tid] = o; sidx[tid] = oi;
            }
        }
        __syncthreads();
    }
    const float rowmax = sval[0];
    const int argmax = sidx[0];
    __syncthreads();

    float e[4]; float z = 0.f;
    #pragma unroll
    for (int r = 0; r < 4; ++r) { e[r] = expf(l[r] - rowmax); z += e[r]; }

    sred[tid] = z; __syncthreads();
    for (int s = 128; s > 0; s >>= 1) {
        if (tid < s) sred[tid] += sred[tid + s];
        __syncthreads();
    }
    const float Z = sred[0];
    __syncthreads();

    const float invZ = 1.0f / Z;
    float p[4]; float msum = 0.f;
    #pragma unroll
    for (int r = 0; r < 4; ++r) {
        p[r] = e[r] * invZ;
        if (p[r] > 0.1f) msum += p[r];
    }
    sred[tid] = msum; __syncthreads();
    for (int s = 128; s > 0; s >>= 1) {
        if (tid < s) sred[tid] += sred[tid + s];
        __syncthreads();
    }
    const float sumMask = sred[0];

    if (sumMask > 0.f) {
        const float inv = 1.0f / sumMask;
        #pragma unroll
        for (int r = 0; r < 4; ++r)
            Pr[tid + 256 * r] = (p[r] > 0.1f) ? p[r] * inv : 0.f;
    } else {
        #pragma unroll
        for (int r = 0; r < 4; ++r)
            Pr[tid + 256 * r] = ((tid + 256 * r) == argmax) ? 1.0f : 0.f;
    }
}

// ---------------------------------------------------------------------------
// AV: O[b, i, h*64 + d] = sum_j F[bh,i,j] * V[bh,j,d].  Per (bh): M=1024,
// N=64, K=1024.  grid (S/64, B*H), 64x64 output tile, BK=32, 256 threads.
// ---------------------------------------------------------------------------
__global__ __launch_bounds__(256) void av_kernel(
    const float* __restrict__ F, const float* __restrict__ qkv,
    float* __restrict__ O)
{
    const int bh = blockIdx.y;
    const int b = bh / Hh, h = bh % Hh;
    const int i0 = blockIdx.x * 64;

    const float* Fb = F + ((size_t)bh * Ss + i0) * Ss;                     // [64, 1024]
    const float* Vb = qkv + (size_t)(b * Ss) * QKVN + 2 * Ee + h * DH;     // stride QKVN

    __shared__ float Fs[64][33];       // [i][k]
    __shared__ float Vs[32][65];       // [k][d]

    const int tid = threadIdx.x;
    const int fRow = tid / 8;            // 0..31
    const int fCol = (tid % 8) * 4;      // 0..28
    const int vRow = tid / 16;           // 0..15
    const int vCol = (tid % 16) * 4;     // 0..60

    const int ti = (tid / 16) * 4;
    const int tj = (tid % 16) * 4;
    float acc[4][4] = {};

    for (int k0 = 0; k0 < Ss; k0 += 32) {
        #pragma unroll
        for (int r = 0; r < 64; r += 32) {
            float4 v = *(const float4*)(Fb + (size_t)(fRow + r) * Ss + k0 + fCol);
            Fs[fRow + r][fCol + 0] = v.x; Fs[fRow + r][fCol + 1] = v.y;
            Fs[fRow + r][fCol + 2] = v.z; Fs[fRow + r][fCol + 3] = v.w;
        }
        #pragma unroll
        for (int r = 0; r < 32; r += 16) {
            float4 v = *(const float4*)(Vb + (size_t)(k0 + vRow + r) * QKVN + vCol);
            Vs[vRow + r][vCol + 0] = v.x; Vs[vRow + r][vCol + 1] = v.y;
            Vs[vRow + r][vCol + 2] = v.z; Vs[vRow + r][vCol + 3] = v.w;
        }
        __syncthreads();

        #pragma unroll
        for (int k = 0; k < 32; ++k) {
            float rm[4], rn[4];
            #pragma unroll
            for (int i = 0; i < 4; ++i) rm[i] = Fs[ti + i][k];
            #pragma unroll
            for (int j = 0; j < 4; ++j) rn[j] = Vs[k][tj + j];
            #pragma unroll
            for (int i = 0; i < 4; ++i)
                #pragma unroll
                for (int j = 0; j < 4; ++j)
                    acc[i][j] += rm[i] * rn[j];
        }
        __syncthreads();
    }

    #pragma unroll
    for (int i = 0; i < 4; ++i) {
        float4 v;
        v.x = acc[i][0]; v.y = acc[i][1]; v.z = acc[i][2]; v.w = acc[i][3];
        *(float4*)(O + (size_t)(b * Ss + i0 + ti + i) * Ee + h * DH + tj) = v;
    }
}

// ---------------------------------------------------------------------------
// Launch
// ---------------------------------------------------------------------------
static float* sym_addr(const void* sym)
{
    void* p = nullptr;
    cudaGetSymbolAddress(&p, sym);
    return (float*)p;
}

extern "C" void kernel_launch(void* const* d_in, const int* in_sizes, int n_in,
                              void* d_out, int out_size)
{
    const float* x      = (const float*)d_in[0];
    const float* w_qkv  = (const float*)d_in[1];
    const float* b_qkv  = (const float*)d_in[2];
    const float* w_proj = (const float*)d_in[3];
    const float* b_proj = (const float*)d_in[4];

    float* qkv = sym_addr(g_qkv);
    float* ao  = sym_addr(g_ao);

    const size_t OUT_N  = (size_t)Bb * Ss * Ee;        // 4194304
    const size_t ATTN_N = (size_t)Bb * Hh * Ss * Ss;   // 67108864

    float* out = (float*)d_out;
    float* P;
    float* mainOut;
    if ((size_t)out_size >= OUT_N + ATTN_N) {
        mainOut = out;
        P = out + OUT_N;                 // filtered_attn written in place
    } else if ((size_t)out_size == ATTN_N) {
        mainOut = sym_addr(g_spill);     // attn-only output
        P = out;
    } else {
        mainOut = out;                   // out-only output
        P = sym_addr(g_P);
    }

    // 1. QKV projection: [4096,1024] @ [1024,3072] + bias
    {
        dim3 grid(QKVN / 128, MROWS / 128);
        sgemm_bias_kernel<<<grid, 256>>>(x, w_qkv, b_qkv, qkv, MROWS, QKVN, Ee);
    }
    // 2. QK^T logits
    {
        dim3 grid(Ss / 64, Ss / 64, Bb * Hh);
        qk_logits_kernel<<<grid, 256>>>(qkv, P);
    }
    // 3. fused softmax + threshold mask + renorm (in place)
    softmax_mask_kernel<<<Bb * Hh * Ss, 256>>>(P);
    // 4. AV
    {
        dim3 grid(Ss / 64, Bb * Hh);
        av_kernel<<<grid, 256>>>(P, qkv, ao);
    }
    // 5. output projection: [4096,1024] @ [1024,1024] + bias
    {
        dim3 grid(Ee / 128, MROWS / 128);
        sgemm_bias_kernel<<<grid, 256>>>(ao, w_proj, b_proj, mainOut, MROWS, Ee, Ee);
    }
}

// round 2
// speedup vs baseline: 1.3180x; 1.3180x over previous
#include <cuda_runtime.h>
#include <math.h>

// Problem constants
#define Bb 4
#define Ss 1024
#define Ee 1024
#define Hh 16
#define DH 64
#define MROWS (Bb * Ss)      // 4096
#define QKVN (3 * Ee)        // 3072

// Scratch (device globals are the allowed scratch mechanism)
__device__ float g_qkv[(size_t)MROWS * QKVN];         // 50.3 MB
__device__ float g_P[(size_t)Bb * Hh * Ss * Ss];      // 268 MB (logits/probs/filtered)
__device__ float g_ao[(size_t)MROWS * Ee];            // 16.8 MB (attn output)
__device__ float g_spill[(size_t)MROWS * Ee];         // fallback main-out if not in d_out

// ---------------------------------------------------------------------------
// tf32x3 tensor-core GEMM (fp32-accurate):  C = alpha * A @ B(^T) + bias
//   A: row-major M x K (leading dim lda)
//   B: !transB -> row-major K x N (ldb);  transB -> row-major N x K (ldb)
//   Block tile 128x64, BK=32, 256 threads (8 warps, 4x2), warp tile 32x32.
//   Each fp32 value split x = hi(tf32) + lo(tf32); 3 MMA passes:
//   hi*hi + hi*lo + lo*hi  ->  ~1e-7 relative accuracy (cuBLAS tf32x3 scheme).
// mode: 0 = plain (gridDim.z==1), 1 = QK^T per (b,h), 2 = AV per (b,h)
// ---------------------------------------------------------------------------

__device__ __forceinline__ unsigned f2tf32(float x) {
    unsigned u;
    asm("cvt.rna.tf32.f32 %0, %1;" : "=r"(u) : "f"(x));
    return u;
}

#define MMA_TF32(cc, aa, bb)                                              \
    asm volatile(                                                          \
        "mma.sync.aligned.m16n8k8.row.col.f32.tf32.tf32.f32 "             \
        "{%0,%1,%2,%3}, {%4,%5,%6,%7}, {%8,%9}, {%0,%1,%2,%3};"           \
        : "+f"(cc[0]), "+f"(cc[1]), "+f"(cc[2]), "+f"(cc[3])              \
        : "r"(aa[0]), "r"(aa[1]), "r"(aa[2]), "r"(aa[3]),                 \
          "r"(bb[0]), "r"(bb[1]))

// smem strides (padding chosen for conflict-free fragment loads)
#define ASTR 36   // [128][36]   bank = 4*m + k  -> conflict-free frags
#define BSTR 72   // [32][72]    bank = 8*k + n  -> conflict-free frags

#define SMEM_FLOATS (128 * ASTR * 2 + 32 * BSTR * 2)   // 13824 floats = 55296 B

__global__ __launch_bounds__(256) void gemm_tf32x3_kernel(
    const float* __restrict__ A, const float* __restrict__ B,
    const float* __restrict__ bias, float* __restrict__ C,
    int M, int N, int K, int lda, int ldb, int ldc,
    int mode, int transB, float alpha)
{
    extern __shared__ float sm[];
    float* Ah = sm;                       // [128][ASTR]
    float* Al = Ah + 128 * ASTR;
    float* Bh = Al + 128 * ASTR;          // [32][BSTR]
    float* Bl = Bh + 32 * BSTR;

    const int tid = threadIdx.x;
    const int z = blockIdx.z;

    // resolve per-batch base pointers
    const float* Ab;
    const float* Bbp;
    float* Cb;
    if (mode == 0) {
        Ab = A; Bbp = B; Cb = C;
    } else if (mode == 1) {               // QK^T: A=Q slice, B=K slice, C=P
        const int b = z >> 4, h = z & 15;
        Ab  = A + (size_t)b * Ss * QKVN + h * DH;
        Bbp = B + (size_t)b * Ss * QKVN + Ee + h * DH;
        Cb  = C + (size_t)z * Ss * Ss;
    } else {                              // AV: A=F rows, B=V slice, C=ao slice
        const int b = z >> 4, h = z & 15;
        Ab  = A + (size_t)z * Ss * Ss;
        Bbp = B + (size_t)b * Ss * QKVN + 2 * Ee + h * DH;
        Cb  = C + (size_t)(b * Ss) * Ee + h * DH;
    }

    const float* Abase = Ab + (size_t)blockIdx.y * 128 * lda;
    const float* Bbase = transB ? (Bbp + (size_t)blockIdx.x * 64 * ldb)
                                : (Bbp + blockIdx.x * 64);

    const int warp = tid >> 5, lane = tid & 31;
    const int wm = warp >> 1, wn = warp & 1;       // 4 x 2 warp grid
    const int g = lane >> 2, t = lane & 3;

    float acc[2][4][4];
    #pragma unroll
    for (int mt = 0; mt < 2; ++mt)
        #pragma unroll
        for (int nt = 0; nt < 4; ++nt)
            #pragma unroll
            for (int r = 0; r < 4; ++r) acc[mt][nt][r] = 0.f;

    for (int k0 = 0; k0 < K; k0 += 32) {
        // ---- load A tile 128x32, split hi/lo ----
        {
            const int row = tid >> 3;
            const int col = (tid & 7) * 4;
            #pragma unroll
            for (int r = 0; r < 4; ++r) {
                const int rr = row + r * 32;
                float4 v = *(const float4*)(Abase + (size_t)rr * lda + k0 + col);
                float xs[4] = {v.x, v.y, v.z, v.w};
                #pragma unroll
                for (int i = 0; i < 4; ++i) {
                    float hf = __uint_as_float(f2tf32(xs[i]));
                    Ah[rr * ASTR + col + i] = hf;
                    Al[rr * ASTR + col + i] = __uint_as_float(f2tf32(xs[i] - hf));
                }
            }
        }
        // ---- load B tile (stored as Bh[k][n]) ----
        if (!transB) {
            const int kr = tid >> 4;
            const int col = (tid & 15) * 4;
            #pragma unroll
            for (int r = 0; r < 2; ++r) {
                const int kk = kr + r * 16;
                float4 v = *(const float4*)(Bbase + (size_t)(k0 + kk) * ldb + col);
                float xs[4] = {v.x, v.y, v.z, v.w};
                #pragma unroll
                for (int i = 0; i < 4; ++i) {
                    float hf = __uint_as_float(f2tf32(xs[i]));
                    Bh[kk * BSTR + col + i] = hf;
                    Bl[kk * BSTR + col + i] = __uint_as_float(f2tf32(xs[i] - hf));
                }
            }
        } else {
            #pragma unroll
            for (int r = 0; r < 2; ++r) {
                const int idx = tid + r * 256;
                const int n = idx & 63;
                const int kq = (idx >> 6) * 4;
                float4 v = *(const float4*)(Bbase + (size_t)n * ldb + k0 + kq);
                float xs[4] = {v.x, v.y, v.z, v.w};
                #pragma unroll
                for (int i = 0; i < 4; ++i) {
                    float hf = __uint_as_float(f2tf32(xs[i]));
                    Bh[(kq + i) * BSTR + n] = hf;
                    Bl[(kq + i) * BSTR + n] = __uint_as_float(f2tf32(xs[i] - hf));
                }
            }
        }
        __syncthreads();

        // ---- MMA over 4 k-slices of 8 ----
        #pragma unroll
        for (int kk = 0; kk < 32; kk += 8) {
            unsigned a_h[2][4], a_l[2][4];
            const int mrow = wm * 32 + g;
            const int kcol = kk + t;
            #pragma unroll
            for (int mt = 0; mt < 2; ++mt) {
                const int m0 = mrow + mt * 16;
                a_h[mt][0] = __float_as_uint(Ah[(m0)     * ASTR + kcol]);
                a_h[mt][1] = __float_as_uint(Ah[(m0 + 8) * ASTR + kcol]);
                a_h[mt][2] = __float_as_uint(Ah[(m0)     * ASTR + kcol + 4]);
                a_h[mt][3] = __float_as_uint(Ah[(m0 + 8) * ASTR + kcol + 4]);
                a_l[mt][0] = __float_as_uint(Al[(m0)     * ASTR + kcol]);
                a_l[mt][1] = __float_as_uint(Al[(m0 + 8) * ASTR + kcol]);
                a_l[mt][2] = __float_as_uint(Al[(m0)     * ASTR + kcol + 4]);
                a_l[mt][3] = __float_as_uint(Al[(m0 + 8) * ASTR + kcol + 4]);
            }
            unsigned b_h[4][2], b_l[4][2];
            const int krow = kk + t;
            const int ncol = wn * 32 + g;
            #pragma unroll
            for (int nt = 0; nt < 4; ++nt) {
                const int n0 = ncol + nt * 8;
                b_h[nt][0] = __float_as_uint(Bh[(krow)     * BSTR + n0]);
                b_h[nt][1] = __float_as_uint(Bh[(krow + 4) * BSTR + n0]);
                b_l[nt][0] = __float_as_uint(Bl[(krow)     * BSTR + n0]);
                b_l[nt][1] = __float_as_uint(Bl[(krow + 4) * BSTR + n0]);
            }
            #pragma unroll
            for (int mt = 0; mt < 2; ++mt)
                #pragma unroll
                for (int nt = 0; nt < 4; ++nt) {
                    MMA_TF32(acc[mt][nt], a_h[mt], b_h[nt]);
                    MMA_TF32(acc[mt][nt], a_h[mt], b_l[nt]);
                    MMA_TF32(acc[mt][nt], a_l[mt], b_h[nt]);
                }
        }
        __syncthreads();
    }

    // ---- epilogue ----
    #pragma unroll
    for (int mt = 0; mt < 2; ++mt) {
        #pragma unroll
        for (int nt = 0; nt < 4; ++nt) {
            const int row0 = blockIdx.y * 128 + wm * 32 + mt * 16 + g;
            const int col  = blockIdx.x * 64 + wn * 32 + nt * 8 + t * 2;
            float bv0 = 0.f, bv1 = 0.f;
            if (bias) { bv0 = bias[col]; bv1 = bias[col + 1]; }
            float2 v0 = make_float2(acc[mt][nt][0] * alpha + bv0,
                                    acc[mt][nt][1] * alpha + bv1);
            *(float2*)(Cb + (size_t)row0 * ldc + col) = v0;
            float2 v1 = make_float2(acc[mt][nt][2] * alpha + bv0,
                                    acc[mt][nt][3] * alpha + bv1);
            *(float2*)(Cb + (size_t)(row0 + 8) * ldc + col) = v1;
        }
    }
}

// ---------------------------------------------------------------------------
// Fused softmax + threshold mask + renormalize, in place on P (known good).
// ---------------------------------------------------------------------------
__global__ __launch_bounds__(256) void softmax_mask_kernel(float* __restrict__ P)
{
    const size_t row = blockIdx.x;
    float* Pr = P + row * (size_t)Ss;
    const int tid = threadIdx.x;

    float l[4];
    #pragma unroll
    for (int r = 0; r < 4; ++r) l[r] = Pr[tid + 256 * r];

    float m = l[0]; int mi = tid;
    #pragma unroll
    for (int r = 1; r < 4; ++r) {
        if (l[r] > m) { m = l[r]; mi = tid + 256 * r; }
    }

    __shared__ float sval[256];
    __shared__ int   sidx[256];
    __shared__ float sred[256];

    sval[tid] = m; sidx[tid] = mi;
    __syncthreads();
    for (int s = 128; s > 0; s >>= 1) {
        if (tid < s) {
            float o = sval[tid + s]; int oi = sidx[tid + s];
            if (o > sval[tid] || (o == sval[tid] && oi < sidx[tid])) {
                sval[tid] = o; sidx[tid] = oi;
            }
        }
        __syncthreads();
    }
    const float rowmax = sval[0];
    const int argmax = sidx[0];
    __syncthreads();

    float e[4]; float zsum = 0.f;
    #pragma unroll
    for (int r = 0; r < 4; ++r) { e[r] = expf(l[r] - rowmax); zsum += e[r]; }

    sred[tid] = zsum; __syncthreads();
    for (int s = 128; s > 0; s >>= 1) {
        if (tid < s) sred[tid] += sred[tid + s];
        __syncthreads();
    }
    const float Z = sred[0];
    __syncthreads();

    const float invZ = 1.0f / Z;
    float p[4]; float msum = 0.f;
    #pragma unroll
    for (int r = 0; r < 4; ++r) {
        p[r] = e[r] * invZ;
        if (p[r] > 0.1f) msum += p[r];
    }
    sred[tid] = msum; __syncthreads();
    for (int s = 128; s > 0; s >>= 1) {
        if (tid < s) sred[tid] += sred[tid + s];
        __syncthreads();
    }
    const float sumMask = sred[0];

    if (sumMask > 0.f) {
        const float inv = 1.0f / sumMask;
        #pragma unroll
        for (int r = 0; r < 4; ++r)
            Pr[tid + 256 * r] = (p[r] > 0.1f) ? p[r] * inv : 0.f;
    } else {
        #pragma unroll
        for (int r = 0; r < 4; ++r)
            Pr[tid + 256 * r] = ((tid + 256 * r) == argmax) ? 1.0f : 0.f;
    }
}

// ---------------------------------------------------------------------------
// Launch
// ---------------------------------------------------------------------------
static float* sym_addr(const void* sym)
{
    void* p = nullptr;
    cudaGetSymbolAddress(&p, sym);
    return (float*)p;
}

extern "C" void kernel_launch(void* const* d_in, const int* in_sizes, int n_in,
                              void* d_out, int out_size)
{
    const float* x      = (const float*)d_in[0];
    const float* w_qkv  = (const float*)d_in[1];
    const float* b_qkv  = (const float*)d_in[2];
    const float* w_proj = (const float*)d_in[3];
    const float* b_proj = (const float*)d_in[4];

    float* qkv = sym_addr(g_qkv);
    float* ao  = sym_addr(g_ao);

    const size_t OUT_N  = (size_t)Bb * Ss * Ee;        // 4194304
    const size_t ATTN_N = (size_t)Bb * Hh * Ss * Ss;   // 67108864

    float* out = (float*)d_out;
    float* P;
    float* mainOut;
    if ((size_t)out_size >= OUT_N + ATTN_N) {
        mainOut = out;
        P = out + OUT_N;                 // filtered_attn written in place
    } else if ((size_t)out_size == ATTN_N) {
        mainOut = sym_addr(g_spill);     // attn-only output
        P = out;
    } else {
        mainOut = out;                   // out-only output
        P = sym_addr(g_P);
    }

    const size_t smemBytes = SMEM_FLOATS * sizeof(float);  // 55296
    cudaFuncSetAttribute(gemm_tf32x3_kernel,
                         cudaFuncAttributeMaxDynamicSharedMemorySize,
                         (int)smemBytes);

    // 1. QKV projection: [4096,1024] @ [1024,3072] + bias
    {
        dim3 grid(QKVN / 64, MROWS / 128, 1);
        gemm_tf32x3_kernel<<<grid, 256, smemBytes>>>(
            x, w_qkv, b_qkv, qkv, MROWS, QKVN, Ee,
            Ee, QKVN, QKVN, /*mode=*/0, /*transB=*/0, 1.0f);
    }
    // 2. QK^T logits: per (b,h): [1024,64] @ [1024,64]^T, alpha = 0.125
    {
        dim3 grid(Ss / 64, Ss / 128, Bb * Hh);
        gemm_tf32x3_kernel<<<grid, 256, smemBytes>>>(
            qkv, qkv, nullptr, P, Ss, Ss, DH,
            QKVN, QKVN, Ss, /*mode=*/1, /*transB=*/1, 0.125f);
    }
    // 3. fused softmax + threshold mask + renorm (in place)
    softmax_mask_kernel<<<Bb * Hh * Ss, 256>>>(P);
    // 4. AV: per (b,h): [1024,1024] @ [1024,64]
    {
        dim3 grid(DH / 64, Ss / 128, Bb * Hh);
        gemm_tf32x3_kernel<<<grid, 256, smemBytes>>>(
            P, qkv, nullptr, ao, Ss, DH, Ss,
            Ss, QKVN, Ee, /*mode=*/2, /*transB=*/0, 1.0f);
    }
    // 5. output projection: [4096,1024] @ [1024,1024] + bias
    {
        dim3 grid(Ee / 64, MROWS / 128, 1);
        gemm_tf32x3_kernel<<<grid, 256, smemBytes>>>(
            ao, w_proj, b_proj, mainOut, MROWS, Ee, Ee,
            Ee, Ee, Ee, /*mode=*/0, /*transB=*/0, 1.0f);
    }
}

// round 3
// speedup vs baseline: 1.4650x; 1.1116x over previous
#include <cuda_runtime.h>
#include <math.h>

// Problem constants
#define Bb 4
#define Ss 1024
#define Ee 1024
#define Hh 16
#define DH 64
#define MROWS (Bb * Ss)      // 4096
#define QKVN (3 * Ee)        // 3072

// Scratch (device globals are the allowed scratch mechanism)
__device__ float g_qkv[(size_t)MROWS * QKVN];         // 50.3 MB
__device__ float g_P[(size_t)Bb * Hh * Ss * Ss];      // 268 MB
__device__ float g_ao[(size_t)MROWS * Ee];            // 16.8 MB
__device__ float g_spill[(size_t)MROWS * Ee];

// ---------------------------------------------------------------------------
// tf32x3 tensor-core GEMM, cp.async double-buffered.
//   C = alpha * A @ B(^T) + bias
//   Block tile 128x64, BK=32, 256 threads (8 warps 4x2), warp tile 32x32.
//   Raw fp32 in smem; hi/lo tf32 split done in registers per fragment.
// MODE: 0 = plain, 1 = QK^T per (b,h), 2 = AV per (b,h)
// ---------------------------------------------------------------------------

__device__ __forceinline__ unsigned f2tf32(float x) {
    unsigned u;
    asm("cvt.rna.tf32.f32 %0, %1;" : "=r"(u) : "f"(x));
    return u;
}

__device__ __forceinline__ void split32(float x, unsigned& h, unsigned& l) {
    unsigned hu = f2tf32(x);
    h = hu;
    l = f2tf32(x - __uint_as_float(hu));
}

#define MMA_TF32(cc, aa, bb)                                              \
    asm volatile(                                                          \
        "mma.sync.aligned.m16n8k8.row.col.f32.tf32.tf32.f32 "             \
        "{%0,%1,%2,%3}, {%4,%5,%6,%7}, {%8,%9}, {%0,%1,%2,%3};"           \
        : "+f"(cc[0]), "+f"(cc[1]), "+f"(cc[2]), "+f"(cc[3])              \
        : "r"(aa[0]), "r"(aa[1]), "r"(aa[2]), "r"(aa[3]),                 \
          "r"(bb[0]), "r"(bb[1]))

#define CP_ASYNC16(dst, src)                                              \
    asm volatile("cp.async.cg.shared.global [%0], [%1], 16;"              \
                 :: "r"(dst), "l"(src))
#define CP_COMMIT() asm volatile("cp.async.commit_group;")
#define CP_WAIT_ALL() asm volatile("cp.async.wait_group 0;")

// smem strides (conflict-free fragment loads)
#define ASTR 36                     // A/[transB]B stored [row][k], stride 36
#define BSTR 72                     // B stored [k][n], stride 72
#define A_TILE (128 * ASTR)         // 4608 floats
#define B_TILE 2304                 // 32*72 == 64*36
#define SMEM_FLOATS (2 * A_TILE + 2 * B_TILE)   // 13824 floats = 55296 B

template <int MODE, int TRANSB>
__device__ __forceinline__ void load_tiles(
    const float* __restrict__ Abase, const float* __restrict__ Bbase,
    int lda, int ldb, int k0, float* As, float* Bs, int tid)
{
    // A: 128 x 32
    {
        const int row = tid >> 3;
        const int col = (tid & 7) * 4;
        const float* src = Abase + (size_t)row * lda + k0 + col;
        unsigned dst = (unsigned)__cvta_generic_to_shared(As + row * ASTR + col);
        #pragma unroll
        for (int r = 0; r < 4; ++r)
            CP_ASYNC16(dst + r * 32 * ASTR * 4, src + (size_t)r * 32 * lda);
    }
    if (!TRANSB) {
        // B: 32 x 64 stored [k][n] stride BSTR
        const int kr = tid >> 4;
        const int col = (tid & 15) * 4;
        const float* src = Bbase + (size_t)(k0 + kr) * ldb + col;
        unsigned dst = (unsigned)__cvta_generic_to_shared(Bs + kr * BSTR + col);
        #pragma unroll
        for (int r = 0; r < 2; ++r)
            CP_ASYNC16(dst + r * 16 * BSTR * 4, src + (size_t)r * 16 * ldb);
    } else {
        // B: 64 x 32 stored [n][k] stride ASTR
        const int n = tid >> 3;
        const int col = (tid & 7) * 4;
        const float* src = Bbase + (size_t)n * ldb + k0 + col;
        unsigned dst = (unsigned)__cvta_generic_to_shared(Bs + n * ASTR + col);
        #pragma unroll
        for (int r = 0; r < 2; ++r)
            CP_ASYNC16(dst + r * 32 * ASTR * 4, src + (size_t)r * 32 * ldb);
    }
}

template <int MODE, int TRANSB>
__global__ __launch_bounds__(256) void gemm_tf32x3_kernel(
    const float* __restrict__ A, const float* __restrict__ B,
    const float* __restrict__ bias, float* __restrict__ C,
    int K, int lda, int ldb, int ldc, float alpha)
{
    extern __shared__ float sm[];
    float* As = sm;                       // [2][A_TILE]
    float* Bs = sm + 2 * A_TILE;          // [2][B_TILE]

    const int tid = threadIdx.x;
    const int z = blockIdx.z;

    const float* Ab;
    const float* Bbp;
    float* Cb;
    if (MODE == 0) {
        Ab = A; Bbp = B; Cb = C;
    } else if (MODE == 1) {               // QK^T
        const int b = z >> 4, h = z & 15;
        Ab  = A + (size_t)b * Ss * QKVN + h * DH;
        Bbp = B + (size_t)b * Ss * QKVN + Ee + h * DH;
        Cb  = C + (size_t)z * Ss * Ss;
    } else {                              // AV
        const int b = z >> 4, h = z & 15;
        Ab  = A + (size_t)z * Ss * Ss;
        Bbp = B + (size_t)b * Ss * QKVN + 2 * Ee + h * DH;
        Cb  = C + (size_t)(b * Ss) * Ee + h * DH;
    }

    const float* Abase = Ab + (size_t)blockIdx.y * 128 * lda;
    const float* Bbase = TRANSB ? (Bbp + (size_t)blockIdx.x * 64 * ldb)
                                : (Bbp + blockIdx.x * 64);

    const int warp = tid >> 5, lane = tid & 31;
    const int wm = warp >> 1, wn = warp & 1;
    const int g = lane >> 2, t = lane & 3;

    float acc[2][4][4];
    #pragma unroll
    for (int mt = 0; mt < 2; ++mt)
        #pragma unroll
        for (int nt = 0; nt < 4; ++nt)
            #pragma unroll
            for (int r = 0; r < 4; ++r) acc[mt][nt][r] = 0.f;

    const int KT = K >> 5;

    load_tiles<MODE, TRANSB>(Abase, Bbase, lda, ldb, 0, As, Bs, tid);
    CP_COMMIT();

    for (int kt = 0; kt < KT; ++kt) {
        CP_WAIT_ALL();
        __syncthreads();

        if (kt + 1 < KT) {
            load_tiles<MODE, TRANSB>(Abase, Bbase, lda, ldb, (kt + 1) * 32,
                                     As + ((kt + 1) & 1) * A_TILE,
                                     Bs + ((kt + 1) & 1) * B_TILE, tid);
            CP_COMMIT();
        }

        const float* Ac = As + (kt & 1) * A_TILE;
        const float* Bc = Bs + (kt & 1) * B_TILE;

        #pragma unroll
        for (int kk = 0; kk < 32; kk += 8) {
            unsigned a_h[2][4], a_l[2][4];
            const int kcol = kk + t;
            #pragma unroll
            for (int mt = 0; mt < 2; ++mt) {
                const int m0 = wm * 32 + mt * 16 + g;
                split32(Ac[m0 * ASTR + kcol],           a_h[mt][0], a_l[mt][0]);
                split32(Ac[(m0 + 8) * ASTR + kcol],     a_h[mt][1], a_l[mt][1]);
                split32(Ac[m0 * ASTR + kcol + 4],       a_h[mt][2], a_l[mt][2]);
                split32(Ac[(m0 + 8) * ASTR + kcol + 4], a_h[mt][3], a_l[mt][3]);
            }
            unsigned b_h[4][2], b_l[4][2];
            #pragma unroll
            for (int nt = 0; nt < 4; ++nt) {
                const int n0 = wn * 32 + nt * 8 + g;
                float y0, y1;
                if (TRANSB) {
                    y0 = Bc[n0 * ASTR + kk + t];
                    y1 = Bc[n0 * ASTR + kk + t + 4];
                } else {
                    y0 = Bc[(kk + t) * BSTR + n0];
                    y1 = Bc[(kk + t + 4) * BSTR + n0];
                }
                split32(y0, b_h[nt][0], b_l[nt][0]);
                split32(y1, b_h[nt][1], b_l[nt][1]);
            }
            #pragma unroll
            for (int mt = 0; mt < 2; ++mt)
                #pragma unroll
                for (int nt = 0; nt < 4; ++nt) {
                    MMA_TF32(acc[mt][nt], a_h[mt], b_h[nt]);
                    MMA_TF32(acc[mt][nt], a_h[mt], b_l[nt]);
                    MMA_TF32(acc[mt][nt], a_l[mt], b_h[nt]);
                }
        }
        __syncthreads();
    }

    // epilogue
    #pragma unroll
    for (int mt = 0; mt < 2; ++mt) {
        #pragma unroll
        for (int nt = 0; nt < 4; ++nt) {
            const int row0 = blockIdx.y * 128 + wm * 32 + mt * 16 + g;
            const int col  = blockIdx.x * 64 + wn * 32 + nt * 8 + t * 2;
            float bv0 = 0.f, bv1 = 0.f;
            if (bias) { bv0 = bias[col]; bv1 = bias[col + 1]; }
            float2 v0 = make_float2(acc[mt][nt][0] * alpha + bv0,
                                    acc[mt][nt][1] * alpha + bv1);
            *(float2*)(Cb + (size_t)row0 * ldc + col) = v0;
            float2 v1 = make_float2(acc[mt][nt][2] * alpha + bv0,
                                    acc[mt][nt][3] * alpha + bv1);
            *(float2*)(Cb + (size_t)(row0 + 8) * ldc + col) = v1;
        }
    }
}

// ---------------------------------------------------------------------------
// Fused softmax + threshold mask + renorm, in place. float4 + warp shuffles.
// One block per row (1024 cols), 256 threads, 4 elems/thread (contiguous).
// ---------------------------------------------------------------------------
__global__ __launch_bounds__(256) void softmax_mask_kernel(float* __restrict__ P)
{
    const size_t row = blockIdx.x;
    float* Pr = P + row * (size_t)Ss;
    const int tid = threadIdx.x;
    const int lane = tid & 31, wid = tid >> 5;

    float4 lv = ((const float4*)Pr)[tid];
    float l[4] = {lv.x, lv.y, lv.z, lv.w};

    __shared__ float sv[8];
    __shared__ int   si[8];

    // ---- max + argmax ----
    float m = l[0]; int mi = 4 * tid;
    #pragma unroll
    for (int r = 1; r < 4; ++r)
        if (l[r] > m) { m = l[r]; mi = 4 * tid + r; }
    #pragma unroll
    for (int o = 16; o > 0; o >>= 1) {
        float ov = __shfl_down_sync(0xffffffffu, m, o);
        int   oi = __shfl_down_sync(0xffffffffu, mi, o);
        if (ov > m || (ov == m && oi < mi)) { m = ov; mi = oi; }
    }
    if (lane == 0) { sv[wid] = m; si[wid] = mi; }
    __syncthreads();
    if (wid == 0) {
        float v = (lane < 8) ? sv[lane] : -3.4e38f;
        int vi  = (lane < 8) ? si[lane] : 0x7fffffff;
        #pragma unroll
        for (int o = 4; o > 0; o >>= 1) {
            float ov = __shfl_down_sync(0xffffffffu, v, o);
            int   oi = __shfl_down_sync(0xffffffffu, vi, o);
            if (ov > v || (ov == v && oi < vi)) { v = ov; vi = oi; }
        }
        if (lane == 0) { sv[0] = v; si[0] = vi; }
    }
    __syncthreads();
    const float rowmax = sv[0];
    const int argmax = si[0];
    __syncthreads();

    // ---- exp + sum ----
    float e[4]; float zsum = 0.f;
    #pragma unroll
    for (int r = 0; r < 4; ++r) { e[r] = expf(l[r] - rowmax); zsum += e[r]; }
    #pragma unroll
    for (int o = 16; o > 0; o >>= 1) zsum += __shfl_xor_sync(0xffffffffu, zsum, o);
    if (lane == 0) sv[wid] = zsum;
    __syncthreads();
    float Z = 0.f;
    #pragma unroll
    for (int w = 0; w < 8; ++w) Z += sv[w];
    __syncthreads();

    // ---- masked sum ----
    const float invZ = 1.0f / Z;
    float p[4]; float msum = 0.f;
    #pragma unroll
    for (int r = 0; r < 4; ++r) {
        p[r] = e[r] * invZ;
        if (p[r] > 0.1f) msum += p[r];
    }
    #pragma unroll
    for (int o = 16; o > 0; o >>= 1) msum += __shfl_xor_sync(0xffffffffu, msum, o);
    if (lane == 0) sv[wid] = msum;
    __syncthreads();
    float sumMask = 0.f;
    #pragma unroll
    for (int w = 0; w < 8; ++w) sumMask += sv[w];

    float4 ov;
    if (sumMask > 0.f) {
        const float inv = 1.0f / sumMask;
        ov.x = (p[0] > 0.1f) ? p[0] * inv : 0.f;
        ov.y = (p[1] > 0.1f) ? p[1] * inv : 0.f;
        ov.z = (p[2] > 0.1f) ? p[2] * inv : 0.f;
        ov.w = (p[3] > 0.1f) ? p[3] * inv : 0.f;
    } else {
        ov.x = (4 * tid + 0 == argmax) ? 1.f : 0.f;
        ov.y = (4 * tid + 1 == argmax) ? 1.f : 0.f;
        ov.z = (4 * tid + 2 == argmax) ? 1.f : 0.f;
        ov.w = (4 * tid + 3 == argmax) ? 1.f : 0.f;
    }
    ((float4*)Pr)[tid] = ov;
}

// ---------------------------------------------------------------------------
// Launch
// ---------------------------------------------------------------------------
static float* sym_addr(const void* sym)
{
    void* p = nullptr;
    cudaGetSymbolAddress(&p, sym);
    return (float*)p;
}

extern "C" void kernel_launch(void* const* d_in, const int* in_sizes, int n_in,
                              void* d_out, int out_size)
{
    const float* x      = (const float*)d_in[0];
    const float* w_qkv  = (const float*)d_in[1];
    const float* b_qkv  = (const float*)d_in[2];
    const float* w_proj = (const float*)d_in[3];
    const float* b_proj = (const float*)d_in[4];

    float* qkv = sym_addr(g_qkv);
    float* ao  = sym_addr(g_ao);

    const size_t OUT_N  = (size_t)Bb * Ss * Ee;
    const size_t ATTN_N = (size_t)Bb * Hh * Ss * Ss;

    float* out = (float*)d_out;
    float* P;
    float* mainOut;
    if ((size_t)out_size >= OUT_N + ATTN_N) {
        mainOut = out;
        P = out + OUT_N;
    } else if ((size_t)out_size == ATTN_N) {
        mainOut = sym_addr(g_spill);
        P = out;
    } else {
        mainOut = out;
        P = sym_addr(g_P);
    }

    const int smemBytes = SMEM_FLOATS * sizeof(float);  // 55296
    cudaFuncSetAttribute(gemm_tf32x3_kernel<0, 0>,
                         cudaFuncAttributeMaxDynamicSharedMemorySize, smemBytes);
    cudaFuncSetAttribute(gemm_tf32x3_kernel<1, 1>,
                         cudaFuncAttributeMaxDynamicSharedMemorySize, smemBytes);
    cudaFuncSetAttribute(gemm_tf32x3_kernel<2, 0>,
                         cudaFuncAttributeMaxDynamicSharedMemorySize, smemBytes);

    // 1. QKV projection: [4096,1024] @ [1024,3072] + bias
    {
        dim3 grid(QKVN / 64, MROWS / 128, 1);
        gemm_tf32x3_kernel<0, 0><<<grid, 256, smemBytes>>>(
            x, w_qkv, b_qkv, qkv, Ee, Ee, QKVN, QKVN, 1.0f);
    }
    // 2. QK^T logits per (b,h), alpha = Dh^-0.5
    {
        dim3 grid(Ss / 64, Ss / 128, Bb * Hh);
        gemm_tf32x3_kernel<1, 1><<<grid, 256, smemBytes>>>(
            qkv, qkv, nullptr, P, DH, QKVN, QKVN, Ss, 0.125f);
    }
    // 3. fused softmax + threshold mask + renorm (in place)
    softmax_mask_kernel<<<Bb * Hh * Ss, 256>>>(P);
    // 4. AV per (b,h): [1024,1024] @ [1024,64]
    {
        dim3 grid(DH / 64, Ss / 128, Bb * Hh);
        gemm_tf32x3_kernel<2, 0><<<grid, 256, smemBytes>>>(
            P, qkv, nullptr, ao, Ss, Ss, QKVN, Ee, 1.0f);
    }
    // 5. output projection: [4096,1024] @ [1024,1024] + bias
    {
        dim3 grid(Ee / 64, MROWS / 128, 1);
        gemm_tf32x3_kernel<0, 0><<<grid, 256, smemBytes>>>(
            ao, w_proj, b_proj, mainOut, Ee, Ee, Ee, Ee, 1.0f);
    }
}

// round 4
// speedup vs baseline: 1.7243x; 1.1770x over previous
#include <cuda_runtime.h>
#include <math.h>

// Problem constants
#define Bb 4
#define Ss 1024
#define Ee 1024
#define Hh 16
#define DH 64
#define MROWS (Bb * Ss)      // 4096
#define QKVN (3 * Ee)        // 3072

// Scratch
__device__ float g_qkv[(size_t)MROWS * QKVN];
__device__ float g_P[(size_t)Bb * Hh * Ss * Ss];
__device__ float g_ao[(size_t)MROWS * Ee];
__device__ float g_spill[(size_t)MROWS * Ee];

// ---------------------------------------------------------------------------
// Common helpers
// ---------------------------------------------------------------------------
__device__ __forceinline__ void split32(float x, unsigned& h, unsigned& l) {
    unsigned hu = __float_as_uint(x) & 0xffffe000u;   // truncate to tf32 mantissa
    h = hu;
    l = __float_as_uint(x - __uint_as_float(hu));     // exact residual (fp32)
}

#define MMA_TF32(cc, aa, bb)                                              \
    asm volatile(                                                          \
        "mma.sync.aligned.m16n8k8.row.col.f32.tf32.tf32.f32 "             \
        "{%0,%1,%2,%3}, {%4,%5,%6,%7}, {%8,%9}, {%0,%1,%2,%3};"           \
        : "+f"(cc[0]), "+f"(cc[1]), "+f"(cc[2]), "+f"(cc[3])              \
        : "r"(aa[0]), "r"(aa[1]), "r"(aa[2]), "r"(aa[3]),                 \
          "r"(bb[0]), "r"(bb[1]))

#define CP_ASYNC16(dst, src)                                              \
    asm volatile("cp.async.cg.shared.global [%0], [%1], 16;"              \
                 :: "r"(dst), "l"(src))
#define CP_COMMIT() asm volatile("cp.async.commit_group;")
#define CP_WAIT_ALL() asm volatile("cp.async.wait_group 0;")

// ===========================================================================
// G1: 128x128 block tile, BK=32, 256 threads (8 warps as 4x2, warp 32x64).
//   A smem [m][k] stride 36; B smem: TRANSB -> [n][k] stride 36,
//   else [k][n] stride 128 with XOR swizzle (col ^ 8*(k&3)).
// MODE: 0 = plain (C=alpha*A@B(+bias)),  1 = QK^T per (b,h)
// ===========================================================================
#define ASTR 36
#define G1_A_TILE (128 * ASTR)        // 4608 floats
#define G1_BT_TILE (128 * ASTR)       // transB tile
#define G1_BN_TILE (32 * 128)         // 4096 floats, swizzled
#define G1_SMEM_T (2 * G1_A_TILE + 2 * G1_BT_TILE)   // 18432 fl = 73728 B
#define G1_SMEM_N (2 * G1_A_TILE + 2 * G1_BN_TILE)   // 17408 fl = 69632 B

template <int TRANSB>
__device__ __forceinline__ void g1_load(
    const float* __restrict__ Abase, const float* __restrict__ Bbase,
    int lda, int ldb, int k0, float* As, float* Bs, int tid)
{
    // A: 128 x 32
    {
        const int row = tid >> 3;
        const int col = (tid & 7) * 4;
        const float* src = Abase + (size_t)row * lda + k0 + col;
        unsigned dst = (unsigned)__cvta_generic_to_shared(As + row * ASTR + col);
        #pragma unroll
        for (int r = 0; r < 4; ++r)
            CP_ASYNC16(dst + r * 32 * ASTR * 4, src + (size_t)r * 32 * lda);
    }
    if (TRANSB) {
        // B: 128 rows (n) x 32 (k), stride 36
        const int row = tid >> 3;
        const int col = (tid & 7) * 4;
        const float* src = Bbase + (size_t)row * ldb + k0 + col;
        unsigned dst = (unsigned)__cvta_generic_to_shared(Bs + row * ASTR + col);
        #pragma unroll
        for (int r = 0; r < 4; ++r)
            CP_ASYNC16(dst + r * 32 * ASTR * 4, src + (size_t)r * 32 * ldb);
    } else {
        // B: 32 (k) x 128 (n), stride 128, XOR swizzle
        #pragma unroll
        for (int r = 0; r < 4; ++r) {
            const int elem = r * 256 + tid;
            const int kr = elem >> 5;
            const int c4 = (elem & 31) * 4;
            const float* src = Bbase + (size_t)(k0 + kr) * ldb + c4;
            unsigned dst = (unsigned)__cvta_generic_to_shared(
                Bs + kr * 128 + (c4 ^ (8 * (kr & 3))));
            CP_ASYNC16(dst, src);
        }
    }
}

template <int MODE, int TRANSB>
__global__ __launch_bounds__(256) void gemm_g1_kernel(
    const float* __restrict__ A, const float* __restrict__ B,
    const float* __restrict__ bias, float* __restrict__ C,
    int K, int lda, int ldb, int ldc, float alpha)
{
    extern __shared__ float sm[];
    const int B_TILE = TRANSB ? G1_BT_TILE : G1_BN_TILE;
    float* As = sm;
    float* Bs = sm + 2 * G1_A_TILE;

    const int tid = threadIdx.x;
    const int z = blockIdx.z;

    const float* Ab;
    const float* Bbp;
    float* Cb;
    if (MODE == 0) {
        Ab = A; Bbp = B; Cb = C;
    } else {                              // QK^T per (b,h)
        const int b = z >> 4, h = z & 15;
        Ab  = A + (size_t)b * Ss * QKVN + h * DH;
        Bbp = B + (size_t)b * Ss * QKVN + Ee + h * DH;
        Cb  = C + (size_t)z * Ss * Ss;
    }

    const float* Abase = Ab + (size_t)blockIdx.y * 128 * lda;
    const float* Bbase = TRANSB ? (Bbp + (size_t)blockIdx.x * 128 * ldb)
                                : (Bbp + blockIdx.x * 128);

    const int warp = tid >> 5, lane = tid & 31;
    const int wm = warp >> 1, wn = warp & 1;     // 4 x 2 warps, warp tile 32x64
    const int g = lane >> 2, t = lane & 3;

    float acc[2][8][4];
    #pragma unroll
    for (int mt = 0; mt < 2; ++mt)
        #pragma unroll
        for (int nt = 0; nt < 8; ++nt)
            #pragma unroll
            for (int r = 0; r < 4; ++r) acc[mt][nt][r] = 0.f;

    const int KT = K >> 5;

    g1_load<TRANSB>(Abase, Bbase, lda, ldb, 0, As, Bs, tid);
    CP_COMMIT();

    for (int kt = 0; kt < KT; ++kt) {
        CP_WAIT_ALL();
        __syncthreads();

        if (kt + 1 < KT) {
            g1_load<TRANSB>(Abase, Bbase, lda, ldb, (kt + 1) * 32,
                            As + ((kt + 1) & 1) * G1_A_TILE,
                            Bs + ((kt + 1) & 1) * B_TILE, tid);
            CP_COMMIT();
        }

        const float* Ac = As + (kt & 1) * G1_A_TILE;
        const float* Bc = Bs + (kt & 1) * B_TILE;

        #pragma unroll
        for (int kk = 0; kk < 32; kk += 8) {
            unsigned a_h[2][4], a_l[2][4];
            const int kcol = kk + t;
            #pragma unroll
            for (int mt = 0; mt < 2; ++mt) {
                const int m0 = wm * 32 + mt * 16 + g;
                split32(Ac[m0 * ASTR + kcol],           a_h[mt][0], a_l[mt][0]);
                split32(Ac[(m0 + 8) * ASTR + kcol],     a_h[mt][1], a_l[mt][1]);
                split32(Ac[m0 * ASTR + kcol + 4],       a_h[mt][2], a_l[mt][2]);
                split32(Ac[(m0 + 8) * ASTR + kcol + 4], a_h[mt][3], a_l[mt][3]);
            }
            unsigned b_h[8][2], b_l[8][2];
            #pragma unroll
            for (int nt = 0; nt < 8; ++nt) {
                const int n0 = wn * 64 + nt * 8 + g;
                float y0, y1;
                if (TRANSB) {
                    y0 = Bc[n0 * ASTR + kk + t];
                    y1 = Bc[n0 * ASTR + kk + t + 4];
                } else {
                    const int nsw = n0 ^ (8 * t);
                    y0 = Bc[(kk + t) * 128 + nsw];
                    y1 = Bc[(kk + t + 4) * 128 + nsw];
                }
                split32(y0, b_h[nt][0], b_l[nt][0]);
                split32(y1, b_h[nt][1], b_l[nt][1]);
            }
            #pragma unroll
            for (int mt = 0; mt < 2; ++mt)
                #pragma unroll
                for (int nt = 0; nt < 8; ++nt) {
                    MMA_TF32(acc[mt][nt], a_h[mt], b_h[nt]);
                    MMA_TF32(acc[mt][nt], a_h[mt], b_l[nt]);
                    MMA_TF32(acc[mt][nt], a_l[mt], b_h[nt]);
                }
        }
        __syncthreads();
    }

    // epilogue
    #pragma unroll
    for (int mt = 0; mt < 2; ++mt) {
        #pragma unroll
        for (int nt = 0; nt < 8; ++nt) {
            const int row0 = blockIdx.y * 128 + wm * 32 + mt * 16 + g;
            const int col  = blockIdx.x * 128 + wn * 64 + nt * 8 + t * 2;
            float bv0 = 0.f, bv1 = 0.f;
            if (bias) { bv0 = bias[col]; bv1 = bias[col + 1]; }
            float2 v0 = make_float2(acc[mt][nt][0] * alpha + bv0,
                                    acc[mt][nt][1] * alpha + bv1);
            *(float2*)(Cb + (size_t)row0 * ldc + col) = v0;
            float2 v1 = make_float2(acc[mt][nt][2] * alpha + bv0,
                                    acc[mt][nt][3] * alpha + bv1);
            *(float2*)(Cb + (size_t)(row0 + 8) * ldc + col) = v1;
        }
    }
}

// ===========================================================================
// G2: AV kernel — 128x64 tile, BK=32, 8 warps (4x2, warp 32x32), min 3 CTAs/SM
// ===========================================================================
#define BSTR 72
#define G2_A_TILE (128 * ASTR)
#define G2_B_TILE (32 * BSTR)
#define G2_SMEM (2 * G2_A_TILE + 2 * G2_B_TILE)   // 13824 fl = 55296 B

__device__ __forceinline__ void g2_load(
    const float* __restrict__ Abase, const float* __restrict__ Bbase,
    int lda, int ldb, int k0, float* As, float* Bs, int tid)
{
    {
        const int row = tid >> 3;
        const int col = (tid & 7) * 4;
        const float* src = Abase + (size_t)row * lda + k0 + col;
        unsigned dst = (unsigned)__cvta_generic_to_shared(As + row * ASTR + col);
        #pragma unroll
        for (int r = 0; r < 4; ++r)
            CP_ASYNC16(dst + r * 32 * ASTR * 4, src + (size_t)r * 32 * lda);
    }
    {
        const int kr = tid >> 4;
        const int col = (tid & 15) * 4;
        const float* src = Bbase + (size_t)(k0 + kr) * ldb + col;
        unsigned dst = (unsigned)__cvta_generic_to_shared(Bs + kr * BSTR + col);
        #pragma unroll
        for (int r = 0; r < 2; ++r)
            CP_ASYNC16(dst + r * 16 * BSTR * 4, src + (size_t)r * 16 * ldb);
    }
}

__global__ __launch_bounds__(256, 3) void gemm_av_kernel(
    const float* __restrict__ A, const float* __restrict__ B,
    float* __restrict__ C)
{
    extern __shared__ float sm[];
    float* As = sm;
    float* Bs = sm + 2 * G2_A_TILE;

    const int tid = threadIdx.x;
    const int z = blockIdx.z;
    const int b = z >> 4, h = z & 15;

    const float* Abase = A + (size_t)z * Ss * Ss + (size_t)blockIdx.y * 128 * Ss;
    const float* Bbase = B + (size_t)b * Ss * QKVN + 2 * Ee + h * DH;
    float* Cb = C + (size_t)(b * Ss) * Ee + h * DH;

    const int warp = tid >> 5, lane = tid & 31;
    const int wm = warp >> 1, wn = warp & 1;
    const int g = lane >> 2, t = lane & 3;

    float acc[2][4][4];
    #pragma unroll
    for (int mt = 0; mt < 2; ++mt)
        #pragma unroll
        for (int nt = 0; nt < 4; ++nt)
            #pragma unroll
            for (int r = 0; r < 4; ++r) acc[mt][nt][r] = 0.f;

    const int KT = Ss >> 5;

    g2_load(Abase, Bbase, Ss, QKVN, 0, As, Bs, tid);
    CP_COMMIT();

    for (int kt = 0; kt < KT; ++kt) {
        CP_WAIT_ALL();
        __syncthreads();

        if (kt + 1 < KT) {
            g2_load(Abase, Bbase, Ss, QKVN, (kt + 1) * 32,
                    As + ((kt + 1) & 1) * G2_A_TILE,
                    Bs + ((kt + 1) & 1) * G2_B_TILE, tid);
            CP_COMMIT();
        }

        const float* Ac = As + (kt & 1) * G2_A_TILE;
        const float* Bc = Bs + (kt & 1) * G2_B_TILE;

        #pragma unroll
        for (int kk = 0; kk < 32; kk += 8) {
            unsigned a_h[2][4], a_l[2][4];
            const int kcol = kk + t;
            #pragma unroll
            for (int mt = 0; mt < 2; ++mt) {
                const int m0 = wm * 32 + mt * 16 + g;
                split32(Ac[m0 * ASTR + kcol],           a_h[mt][0], a_l[mt][0]);
                split32(Ac[(m0 + 8) * ASTR + kcol],     a_h[mt][1], a_l[mt][1]);
                split32(Ac[m0 * ASTR + kcol + 4],       a_h[mt][2], a_l[mt][2]);
                split32(Ac[(m0 + 8) * ASTR + kcol + 4], a_h[mt][3], a_l[mt][3]);
            }
            unsigned b_h[4][2], b_l[4][2];
            #pragma unroll
            for (int nt = 0; nt < 4; ++nt) {
                const int n0 = wn * 32 + nt * 8 + g;
                split32(Bc[(kk + t) * BSTR + n0],     b_h[nt][0], b_l[nt][0]);
                split32(Bc[(kk + t + 4) * BSTR + n0], b_h[nt][1], b_l[nt][1]);
            }
            #pragma unroll
            for (int mt = 0; mt < 2; ++mt)
                #pragma unroll
                for (int nt = 0; nt < 4; ++nt) {
                    MMA_TF32(acc[mt][nt], a_h[mt], b_h[nt]);
                    MMA_TF32(acc[mt][nt], a_h[mt], b_l[nt]);
                    MMA_TF32(acc[mt][nt], a_l[mt], b_h[nt]);
                }
        }
        __syncthreads();
    }

    #pragma unroll
    for (int mt = 0; mt < 2; ++mt) {
        #pragma unroll
        for (int nt = 0; nt < 4; ++nt) {
            const int row0 = blockIdx.y * 128 + wm * 32 + mt * 16 + g;
            const int col  = wn * 32 + nt * 8 + t * 2;
            float2 v0 = make_float2(acc[mt][nt][0], acc[mt][nt][1]);
            *(float2*)(Cb + (size_t)row0 * Ee + col) = v0;
            float2 v1 = make_float2(acc[mt][nt][2], acc[mt][nt][3]);
            *(float2*)(Cb + (size_t)(row0 + 8) * Ee + col) = v1;
        }
    }
}

// ---------------------------------------------------------------------------
// Fused softmax + threshold mask + renorm (in place)
// ---------------------------------------------------------------------------
__global__ __launch_bounds__(256) void softmax_mask_kernel(float* __restrict__ P)
{
    const size_t row = blockIdx.x;
    float* Pr = P + row * (size_t)Ss;
    const int tid = threadIdx.x;
    const int lane = tid & 31, wid = tid >> 5;

    float4 lv = ((const float4*)Pr)[tid];
    float l[4] = {lv.x, lv.y, lv.z, lv.w};

    __shared__ float sv[8];
    __shared__ int   si[8];

    float m = l[0]; int mi = 4 * tid;
    #pragma unroll
    for (int r = 1; r < 4; ++r)
        if (l[r] > m) { m = l[r]; mi = 4 * tid + r; }
    #pragma unroll
    for (int o = 16; o > 0; o >>= 1) {
        float ov = __shfl_down_sync(0xffffffffu, m, o);
        int   oi = __shfl_down_sync(0xffffffffu, mi, o);
        if (ov > m || (ov == m && oi < mi)) { m = ov; mi = oi; }
    }
    if (lane == 0) { sv[wid] = m; si[wid] = mi; }
    __syncthreads();
    if (wid == 0) {
        float v = (lane < 8) ? sv[lane] : -3.4e38f;
        int vi  = (lane < 8) ? si[lane] : 0x7fffffff;
        #pragma unroll
        for (int o = 4; o > 0; o >>= 1) {
            float ov = __shfl_down_sync(0xffffffffu, v, o);
            int   oi = __shfl_down_sync(0xffffffffu, vi, o);
            if (ov > v || (ov == v && oi < vi)) { v = ov; vi = oi; }
        }
        if (lane == 0) { sv[0] = v; si[0] = vi; }
    }
    __syncthreads();
    const float rowmax = sv[0];
    const int argmax = si[0];
    __syncthreads();

    float e[4]; float zsum = 0.f;
    #pragma unroll
    for (int r = 0; r < 4; ++r) { e[r] = expf(l[r] - rowmax); zsum += e[r]; }
    #pragma unroll
    for (int o = 16; o > 0; o >>= 1) zsum += __shfl_xor_sync(0xffffffffu, zsum, o);
    if (lane == 0) sv[wid] = zsum;
    __syncthreads();
    float Z = 0.f;
    #pragma unroll
    for (int w = 0; w < 8; ++w) Z += sv[w];
    __syncthreads();

    const float invZ = 1.0f / Z;
    float p[4]; float msum = 0.f;
    #pragma unroll
    for (int r = 0; r < 4; ++r) {
        p[r] = e[r] * invZ;
        if (p[r] > 0.1f) msum += p[r];
    }
    #pragma unroll
    for (int o = 16; o > 0; o >>= 1) msum += __shfl_xor_sync(0xffffffffu, msum, o);
    if (lane == 0) sv[wid] = msum;
    __syncthreads();
    float sumMask = 0.f;
    #pragma unroll
    for (int w = 0; w < 8; ++w) sumMask += sv[w];

    float4 ov;
    if (sumMask > 0.f) {
        const float inv = 1.0f / sumMask;
        ov.x = (p[0] > 0.1f) ? p[0] * inv : 0.f;
        ov.y = (p[1] > 0.1f) ? p[1] * inv : 0.f;
        ov.z = (p[2] > 0.1f) ? p[2] * inv : 0.f;
        ov.w = (p[3] > 0.1f) ? p[3] * inv : 0.f;
    } else {
        ov.x = (4 * tid + 0 == argmax) ? 1.f : 0.f;
        ov.y = (4 * tid + 1 == argmax) ? 1.f : 0.f;
        ov.z = (4 * tid + 2 == argmax) ? 1.f : 0.f;
        ov.w = (4 * tid + 3 == argmax) ? 1.f : 0.f;
    }
    ((float4*)Pr)[tid] = ov;
}

// ---------------------------------------------------------------------------
// Launch
// ---------------------------------------------------------------------------
static float* sym_addr(const void* sym)
{
    void* p = nullptr;
    cudaGetSymbolAddress(&p, sym);
    return (float*)p;
}

extern "C" void kernel_launch(void* const* d_in, const int* in_sizes, int n_in,
                              void* d_out, int out_size)
{
    const float* x      = (const float*)d_in[0];
    const float* w_qkv  = (const float*)d_in[1];
    const float* b_qkv  = (const float*)d_in[2];
    const float* w_proj = (const float*)d_in[3];
    const float* b_proj = (const float*)d_in[4];

    float* qkv = sym_addr(g_qkv);
    float* ao  = sym_addr(g_ao);

    const size_t OUT_N  = (size_t)Bb * Ss * Ee;
    const size_t ATTN_N = (size_t)Bb * Hh * Ss * Ss;

    float* out = (float*)d_out;
    float* P;
    float* mainOut;
    if ((size_t)out_size >= OUT_N + ATTN_N) {
        mainOut = out;
        P = out + OUT_N;
    } else if ((size_t)out_size == ATTN_N) {
        mainOut = sym_addr(g_spill);
        P = out;
    } else {
        mainOut = out;
        P = sym_addr(g_P);
    }

    const int smemN = G1_SMEM_N * sizeof(float);   // 69632
    const int smemT = G1_SMEM_T * sizeof(float);   // 73728
    const int smemAV = G2_SMEM * sizeof(float);    // 55296
    cudaFuncSetAttribute(gemm_g1_kernel<0, 0>,
                         cudaFuncAttributeMaxDynamicSharedMemorySize, smemN);
    cudaFuncSetAttribute(gemm_g1_kernel<1, 1>,
                         cudaFuncAttributeMaxDynamicSharedMemorySize, smemT);
    cudaFuncSetAttribute(gemm_av_kernel,
                         cudaFuncAttributeMaxDynamicSharedMemorySize, smemAV);

    // 1. QKV projection: [4096,1024] @ [1024,3072] + bias
    {
        dim3 grid(QKVN / 128, MROWS / 128, 1);
        gemm_g1_kernel<0, 0><<<grid, 256, smemN>>>(
            x, w_qkv, b_qkv, qkv, Ee, Ee, QKVN, QKVN, 1.0f);
    }
    // 2. QK^T logits per (b,h), alpha = Dh^-0.5
    {
        dim3 grid(Ss / 128, Ss / 128, Bb * Hh);
        gemm_g1_kernel<1, 1><<<grid, 256, smemT>>>(
            qkv, qkv, nullptr, P, DH, QKVN, QKVN, Ss, 0.125f);
    }
    // 3. fused softmax + threshold mask + renorm (in place)
    softmax_mask_kernel<<<Bb * Hh * Ss, 256>>>(P);
    // 4. AV per (b,h): [1024,1024] @ [1024,64]
    {
        dim3 grid(1, Ss / 128, Bb * Hh);
        gemm_av_kernel<<<grid, 256, smemAV>>>(P, qkv, ao);
    }
    // 5. output projection: [4096,1024] @ [1024,1024] + bias
    {
        dim3 grid(Ee / 128, MROWS / 128, 1);
        gemm_g1_kernel<0, 0><<<grid, 256, smemN>>>(
            ao, w_proj, b_proj, mainOut, Ee, Ee, Ee, Ee, 1.0f);
    }
}

// round 5
// speedup vs baseline: 1.8687x; 1.0837x over previous
#include <cuda_runtime.h>
#include <math.h>

// Problem constants
#define Bb 4
#define Ss 1024
#define Ee 1024
#define Hh 16
#define DH 64
#define MROWS (Bb * Ss)      // 4096
#define QKVN (3 * Ee)        // 3072
#define NROWS (Bb * Hh * Ss) // 65536 attention rows
#define NNZ_CAP 16

// Scratch
__device__ float g_qkv[(size_t)MROWS * QKVN];
__device__ float g_P[(size_t)Bb * Hh * Ss * Ss];
__device__ float g_ao[(size_t)MROWS * Ee];
__device__ float g_spill[(size_t)MROWS * Ee];
__device__ int   g_scnt[NROWS];
__device__ int   g_sidx[(size_t)NROWS * NNZ_CAP];
__device__ float g_sval[(size_t)NROWS * NNZ_CAP];

// ---------------------------------------------------------------------------
// Common helpers
// ---------------------------------------------------------------------------
__device__ __forceinline__ void split32(float x, unsigned& h, unsigned& l) {
    unsigned hu = __float_as_uint(x) & 0xffffe000u;   // truncate to tf32 mantissa
    h = hu;
    l = __float_as_uint(x - __uint_as_float(hu));     // residual
}

#define MMA_TF32(cc, aa, bb)                                              \
    asm volatile(                                                          \
        "mma.sync.aligned.m16n8k8.row.col.f32.tf32.tf32.f32 "             \
        "{%0,%1,%2,%3}, {%4,%5,%6,%7}, {%8,%9}, {%0,%1,%2,%3};"           \
        : "+f"(cc[0]), "+f"(cc[1]), "+f"(cc[2]), "+f"(cc[3])              \
        : "r"(aa[0]), "r"(aa[1]), "r"(aa[2]), "r"(aa[3]),                 \
          "r"(bb[0]), "r"(bb[1]))

#define CP_ASYNC16(dst, src)                                              \
    asm volatile("cp.async.cg.shared.global [%0], [%1], 16;"              \
                 :: "r"(dst), "l"(src))
#define CP_COMMIT() asm volatile("cp.async.commit_group;")
#define CP_WAIT_ALL() asm volatile("cp.async.wait_group 0;")
#define CP_WAIT1() asm volatile("cp.async.wait_group 1;")

// ===========================================================================
// G1: 128x128 block tile, BK=32, 256 threads (8 warps 4x2, warp 32x64).
//   3-stage cp.async pipeline. A smem [m][k] stride 36;
//   B smem: TRANSB -> [n][k] stride 36, else [k][n] stride 128 XOR-swizzled.
// MODE: 0 = plain (C=alpha*A@B(+bias)),  1 = QK^T per (b,h)
// ===========================================================================
#define ASTR 36
#define G1_A_TILE (128 * ASTR)        // 4608 floats
#define G1_BT_TILE (128 * ASTR)       // 4608
#define G1_BN_TILE (32 * 128)         // 4096
#define G1_SMEM_T (3 * (G1_A_TILE + G1_BT_TILE))   // 27648 fl = 110592 B
#define G1_SMEM_N (3 * (G1_A_TILE + G1_BN_TILE))   // 26112 fl = 104448 B

template <int TRANSB>
__device__ __forceinline__ void g1_load(
    const float* __restrict__ Abase, const float* __restrict__ Bbase,
    int lda, int ldb, int k0, float* As, float* Bs, int tid)
{
    // A: 128 x 32
    {
        const int row = tid >> 3;
        const int col = (tid & 7) * 4;
        const float* src = Abase + (size_t)row * lda + k0 + col;
        unsigned dst = (unsigned)__cvta_generic_to_shared(As + row * ASTR + col);
        #pragma unroll
        for (int r = 0; r < 4; ++r)
            CP_ASYNC16(dst + r * 32 * ASTR * 4, src + (size_t)r * 32 * lda);
    }
    if (TRANSB) {
        const int row = tid >> 3;
        const int col = (tid & 7) * 4;
        const float* src = Bbase + (size_t)row * ldb + k0 + col;
        unsigned dst = (unsigned)__cvta_generic_to_shared(Bs + row * ASTR + col);
        #pragma unroll
        for (int r = 0; r < 4; ++r)
            CP_ASYNC16(dst + r * 32 * ASTR * 4, src + (size_t)r * 32 * ldb);
    } else {
        #pragma unroll
        for (int r = 0; r < 4; ++r) {
            const int elem = r * 256 + tid;
            const int kr = elem >> 5;
            const int c4 = (elem & 31) * 4;
            const float* src = Bbase + (size_t)(k0 + kr) * ldb + c4;
            unsigned dst = (unsigned)__cvta_generic_to_shared(
                Bs + kr * 128 + (c4 ^ (8 * (kr & 3))));
            CP_ASYNC16(dst, src);
        }
    }
}

template <int MODE, int TRANSB>
__global__ __launch_bounds__(256) void gemm_g1_kernel(
    const float* __restrict__ A, const float* __restrict__ B,
    const float* __restrict__ bias, float* __restrict__ C,
    int K, int lda, int ldb, int ldc, float alpha)
{
    extern __shared__ float sm[];
    const int B_TILE = TRANSB ? G1_BT_TILE : G1_BN_TILE;
    float* As = sm;                         // 3 stages
    float* Bs = sm + 3 * G1_A_TILE;         // 3 stages

    const int tid = threadIdx.x;
    const int z = blockIdx.z;

    const float* Ab;
    const float* Bbp;
    float* Cb;
    if (MODE == 0) {
        Ab = A; Bbp = B; Cb = C;
    } else {                              // QK^T per (b,h)
        const int b = z >> 4, h = z & 15;
        Ab  = A + (size_t)b * Ss * QKVN + h * DH;
        Bbp = B + (size_t)b * Ss * QKVN + Ee + h * DH;
        Cb  = C + (size_t)z * Ss * Ss;
    }

    const float* Abase = Ab + (size_t)blockIdx.y * 128 * lda;
    const float* Bbase = TRANSB ? (Bbp + (size_t)blockIdx.x * 128 * ldb)
                                : (Bbp + blockIdx.x * 128);

    const int warp = tid >> 5, lane = tid & 31;
    const int wm = warp >> 1, wn = warp & 1;
    const int g = lane >> 2, t = lane & 3;

    float acc[2][8][4];
    #pragma unroll
    for (int mt = 0; mt < 2; ++mt)
        #pragma unroll
        for (int nt = 0; nt < 8; ++nt)
            #pragma unroll
            for (int r = 0; r < 4; ++r) acc[mt][nt][r] = 0.f;

    const int KT = K >> 5;

    // prologue: stage tiles 0 and 1
    g1_load<TRANSB>(Abase, Bbase, lda, ldb, 0, As, Bs, tid);
    CP_COMMIT();
    if (KT > 1) {
        g1_load<TRANSB>(Abase, Bbase, lda, ldb, 32,
                        As + G1_A_TILE, Bs + B_TILE, tid);
        CP_COMMIT();
    }

    for (int kt = 0; kt < KT; ++kt) {
        if (kt < KT - 1) CP_WAIT1(); else CP_WAIT_ALL();
        __syncthreads();

        if (kt + 2 < KT) {
            const int buf = (kt + 2) % 3;
            g1_load<TRANSB>(Abase, Bbase, lda, ldb, (kt + 2) * 32,
                            As + buf * G1_A_TILE, Bs + buf * B_TILE, tid);
            CP_COMMIT();
        }

        const float* Ac = As + (kt % 3) * G1_A_TILE;
        const float* Bc = Bs + (kt % 3) * B_TILE;

        #pragma unroll
        for (int kk = 0; kk < 32; kk += 8) {
            unsigned a_h[2][4], a_l[2][4];
            const int kcol = kk + t;
            #pragma unroll
            for (int mt = 0; mt < 2; ++mt) {
                const int m0 = wm * 32 + mt * 16 + g;
                split32(Ac[m0 * ASTR + kcol],           a_h[mt][0], a_l[mt][0]);
                split32(Ac[(m0 + 8) * ASTR + kcol],     a_h[mt][1], a_l[mt][1]);
                split32(Ac[m0 * ASTR + kcol + 4],       a_h[mt][2], a_l[mt][2]);
                split32(Ac[(m0 + 8) * ASTR + kcol + 4], a_h[mt][3], a_l[mt][3]);
            }
            unsigned b_h[8][2], b_l[8][2];
            #pragma unroll
            for (int nt = 0; nt < 8; ++nt) {
                const int n0 = wn * 64 + nt * 8 + g;
                float y0, y1;
                if (TRANSB) {
                    y0 = Bc[n0 * ASTR + kk + t];
                    y1 = Bc[n0 * ASTR + kk + t + 4];
                } else {
                    const int nsw = n0 ^ (8 * t);
                    y0 = Bc[(kk + t) * 128 + nsw];
                    y1 = Bc[(kk + t + 4) * 128 + nsw];
                }
                split32(y0, b_h[nt][0], b_l[nt][0]);
                split32(y1, b_h[nt][1], b_l[nt][1]);
            }
            #pragma unroll
            for (int mt = 0; mt < 2; ++mt)
                #pragma unroll
                for (int nt = 0; nt < 8; ++nt) {
                    MMA_TF32(acc[mt][nt], a_h[mt], b_h[nt]);
                    MMA_TF32(acc[mt][nt], a_h[mt], b_l[nt]);
                    MMA_TF32(acc[mt][nt], a_l[mt], b_h[nt]);
                }
        }
        __syncthreads();
    }

    // epilogue
    #pragma unroll
    for (int mt = 0; mt < 2; ++mt) {
        #pragma unroll
        for (int nt = 0; nt < 8; ++nt) {
            const int row0 = blockIdx.y * 128 + wm * 32 + mt * 16 + g;
            const int col  = blockIdx.x * 128 + wn * 64 + nt * 8 + t * 2;
            float bv0 = 0.f, bv1 = 0.f;
            if (bias) { bv0 = bias[col]; bv1 = bias[col + 1]; }
            float2 v0 = make_float2(acc[mt][nt][0] * alpha + bv0,
                                    acc[mt][nt][1] * alpha + bv1);
            *(float2*)(Cb + (size_t)row0 * ldc + col) = v0;
            float2 v1 = make_float2(acc[mt][nt][2] * alpha + bv0,
                                    acc[mt][nt][3] * alpha + bv1);
            *(float2*)(Cb + (size_t)(row0 + 8) * ldc + col) = v1;
        }
    }
}

// ---------------------------------------------------------------------------
// Fused softmax + threshold mask + renorm (in place) + sparse nnz extraction.
// Guaranteed <= 9 entries with p > 0.1 per row (sum p = 1); fallback = 1.
// ---------------------------------------------------------------------------
__global__ __launch_bounds__(256) void softmax_mask_kernel(
    float* __restrict__ P, int* __restrict__ scnt,
    int* __restrict__ sidx, float* __restrict__ sval)
{
    const int row = blockIdx.x;
    float* Pr = P + (size_t)row * Ss;
    const int tid = threadIdx.x;
    const int lane = tid & 31, wid = tid >> 5;

    __shared__ float sv[8];
    __shared__ int   si[8];
    __shared__ int   cnt;
    if (tid == 0) cnt = 0;

    float4 lv = ((const float4*)Pr)[tid];
    float l[4] = {lv.x, lv.y, lv.z, lv.w};

    float m = l[0]; int mi = 4 * tid;
    #pragma unroll
    for (int r = 1; r < 4; ++r)
        if (l[r] > m) { m = l[r]; mi = 4 * tid + r; }
    #pragma unroll
    for (int o = 16; o > 0; o >>= 1) {
        float ov = __shfl_down_sync(0xffffffffu, m, o);
        int   oi = __shfl_down_sync(0xffffffffu, mi, o);
        if (ov > m || (ov == m && oi < mi)) { m = ov; mi = oi; }
    }
    if (lane == 0) { sv[wid] = m; si[wid] = mi; }
    __syncthreads();
    if (wid == 0) {
        float v = (lane < 8) ? sv[lane] : -3.4e38f;
        int vi  = (lane < 8) ? si[lane] : 0x7fffffff;
        #pragma unroll
        for (int o = 4; o > 0; o >>= 1) {
            float ov = __shfl_down_sync(0xffffffffu, v, o);
            int   oi = __shfl_down_sync(0xffffffffu, vi, o);
            if (ov > v || (ov == v && oi < vi)) { v = ov; vi = oi; }
        }
        if (lane == 0) { sv[0] = v; si[0] = vi; }
    }
    __syncthreads();
    const float rowmax = sv[0];
    const int argmax = si[0];
    __syncthreads();

    float e[4]; float zsum = 0.f;
    #pragma unroll
    for (int r = 0; r < 4; ++r) { e[r] = expf(l[r] - rowmax); zsum += e[r]; }
    #pragma unroll
    for (int o = 16; o > 0; o >>= 1) zsum += __shfl_xor_sync(0xffffffffu, zsum, o);
    if (lane == 0) sv[wid] = zsum;
    __syncthreads();
    float Z = 0.f;
    #pragma unroll
    for (int w = 0; w < 8; ++w) Z += sv[w];
    __syncthreads();

    const float invZ = 1.0f / Z;
    float p[4]; float msum = 0.f;
    #pragma unroll
    for (int r = 0; r < 4; ++r) {
        p[r] = e[r] * invZ;
        if (p[r] > 0.1f) msum += p[r];
    }
    #pragma unroll
    for (int o = 16; o > 0; o >>= 1) msum += __shfl_xor_sync(0xffffffffu, msum, o);
    if (lane == 0) sv[wid] = msum;
    __syncthreads();
    float sumMask = 0.f;
    #pragma unroll
    for (int w = 0; w < 8; ++w) sumMask += sv[w];

    float4 ov;
    if (sumMask > 0.f) {
        const float inv = 1.0f / sumMask;
        float q[4];
        #pragma unroll
        for (int r = 0; r < 4; ++r)
            q[r] = (p[r] > 0.1f) ? p[r] * inv : 0.f;
        ov.x = q[0]; ov.y = q[1]; ov.z = q[2]; ov.w = q[3];
        #pragma unroll
        for (int r = 0; r < 4; ++r) {
            if (p[r] > 0.1f) {
                int pos = atomicAdd(&cnt, 1);
                if (pos < NNZ_CAP) {
                    sidx[(size_t)row * NNZ_CAP + pos] = 4 * tid + r;
                    sval[(size_t)row * NNZ_CAP + pos] = q[r];
                }
            }
        }
    } else {
        ov.x = (4 * tid + 0 == argmax) ? 1.f : 0.f;
        ov.y = (4 * tid + 1 == argmax) ? 1.f : 0.f;
        ov.z = (4 * tid + 2 == argmax) ? 1.f : 0.f;
        ov.w = (4 * tid + 3 == argmax) ? 1.f : 0.f;
        if (argmax >= 4 * tid && argmax < 4 * tid + 4) {
            int pos = atomicAdd(&cnt, 1);
            if (pos < NNZ_CAP) {
                sidx[(size_t)row * NNZ_CAP + pos] = argmax;
                sval[(size_t)row * NNZ_CAP + pos] = 1.0f;
            }
        }
    }
    ((float4*)Pr)[tid] = ov;

    __syncthreads();
    if (tid == 0) scnt[row] = (cnt < NNZ_CAP) ? cnt : NNZ_CAP;
}

// ---------------------------------------------------------------------------
// Sparse AV: one warp per attention row. out[i,:] = sum_k val_k * V[idx_k,:]
// ---------------------------------------------------------------------------
__global__ __launch_bounds__(256) void av_sparse_kernel(
    const int* __restrict__ scnt, const int* __restrict__ sidx,
    const float* __restrict__ sval, const float* __restrict__ qkv,
    float* __restrict__ ao)
{
    const int r = blockIdx.x * 8 + (threadIdx.x >> 5);
    const int lane = threadIdx.x & 31;

    const int bh = r >> 10, i = r & 1023;
    const int b = bh >> 4, h = bh & 15;
    const float* Vb = qkv + (size_t)b * Ss * QKVN + 2 * Ee + h * DH;

    const int c = scnt[r];
    float a0 = 0.f, a1 = 0.f;
    for (int k = 0; k < c; ++k) {
        const int j = sidx[(size_t)r * NNZ_CAP + k];
        const float v = sval[(size_t)r * NNZ_CAP + k];
        const float* Vr = Vb + (size_t)j * QKVN;
        a0 += v * Vr[lane];
        a1 += v * Vr[lane + 32];
    }
    float* Or = ao + (size_t)(b * Ss + i) * Ee + h * DH;
    Or[lane] = a0;
    Or[lane + 32] = a1;
}

// ---------------------------------------------------------------------------
// Launch
// ---------------------------------------------------------------------------
static float* sym_addr(const void* sym)
{
    void* p = nullptr;
    cudaGetSymbolAddress(&p, sym);
    return (float*)p;
}

extern "C" void kernel_launch(void* const* d_in, const int* in_sizes, int n_in,
                              void* d_out, int out_size)
{
    const float* x      = (const float*)d_in[0];
    const float* w_qkv  = (const float*)d_in[1];
    const float* b_qkv  = (const float*)d_in[2];
    const float* w_proj = (const float*)d_in[3];
    const float* b_proj = (const float*)d_in[4];

    float* qkv = sym_addr(g_qkv);
    float* ao  = sym_addr(g_ao);
    int*   scnt = (int*)sym_addr(g_scnt);
    int*   sidx = (int*)sym_addr(g_sidx);
    float* sval = sym_addr(g_sval);

    const size_t OUT_N  = (size_t)Bb * Ss * Ee;
    const size_t ATTN_N = (size_t)Bb * Hh * Ss * Ss;

    float* out = (float*)d_out;
    float* P;
    float* mainOut;
    if ((size_t)out_size >= OUT_N + ATTN_N) {
        mainOut = out;
        P = out + OUT_N;
    } else if ((size_t)out_size == ATTN_N) {
        mainOut = sym_addr(g_spill);
        P = out;
    } else {
        mainOut = out;
        P = sym_addr(g_P);
    }

    const int smemN = G1_SMEM_N * sizeof(float);   // 104448
    const int smemT = G1_SMEM_T * sizeof(float);   // 110592
    cudaFuncSetAttribute(gemm_g1_kernel<0, 0>,
                         cudaFuncAttributeMaxDynamicSharedMemorySize, smemN);
    cudaFuncSetAttribute(gemm_g1_kernel<1, 1>,
                         cudaFuncAttributeMaxDynamicSharedMemorySize, smemT);

    // 1. QKV projection: [4096,1024] @ [1024,3072] + bias
    {
        dim3 grid(QKVN / 128, MROWS / 128, 1);
        gemm_g1_kernel<0, 0><<<grid, 256, smemN>>>(
            x, w_qkv, b_qkv, qkv, Ee, Ee, QKVN, QKVN, 1.0f);
    }
    // 2. QK^T logits per (b,h), alpha = Dh^-0.5
    {
        dim3 grid(Ss / 128, Ss / 128, Bb * Hh);
        gemm_g1_kernel<1, 1><<<grid, 256, smemT>>>(
            qkv, qkv, nullptr, P, DH, QKVN, QKVN, Ss, 0.125f);
    }
    // 3. fused softmax + threshold mask + renorm + sparse extraction
    softmax_mask_kernel<<<NROWS, 256>>>(P, scnt, sidx, sval);
    // 4. sparse AV (<= 9 nnz per row guaranteed)
    av_sparse_kernel<<<NROWS / 8, 256>>>(scnt, sidx, sval, qkv, ao);
    // 5. output projection: [4096,1024] @ [1024,1024] + bias
    {
        dim3 grid(Ee / 128, MROWS / 128, 1);
        gemm_g1_kernel<0, 0><<<grid, 256, smemN>>>(
            ao, w_proj, b_proj, mainOut, Ee, Ee, Ee, Ee, 1.0f);
    }
}

// round 6
// speedup vs baseline: 2.1145x; 1.1315x over previous
#include <cuda_runtime.h>
#include <math.h>

// Problem constants
#define Bb 4
#define Ss 1024
#define Ee 1024
#define Hh 16
#define DH 64
#define MROWS (Bb * Ss)      // 4096
#define QKVN (3 * Ee)        // 3072
#define NROWS (Bb * Hh * Ss) // 65536 attention rows
#define NNZ_CAP 16

// Scratch
__device__ float g_qkv[(size_t)MROWS * QKVN];
__device__ float g_P[(size_t)Bb * Hh * Ss * Ss];
__device__ float g_ao[(size_t)MROWS * Ee];
__device__ float g_spill[(size_t)MROWS * Ee];
__device__ int   g_scnt[NROWS];
__device__ int   g_sidx[(size_t)NROWS * NNZ_CAP];
__device__ float g_sval[(size_t)NROWS * NNZ_CAP];

// ---------------------------------------------------------------------------
// Common helpers
// ---------------------------------------------------------------------------
__device__ __forceinline__ void split32(float x, unsigned& h, unsigned& l) {
    unsigned hu = __float_as_uint(x) & 0xffffe000u;   // truncate to tf32 mantissa
    h = hu;
    l = __float_as_uint(x - __uint_as_float(hu));     // residual
}

#define MMA_TF32(cc, aa, bb)                                              \
    asm volatile(                                                          \
        "mma.sync.aligned.m16n8k8.row.col.f32.tf32.tf32.f32 "             \
        "{%0,%1,%2,%3}, {%4,%5,%6,%7}, {%8,%9}, {%0,%1,%2,%3};"           \
        : "+f"(cc[0]), "+f"(cc[1]), "+f"(cc[2]), "+f"(cc[3])              \
        : "r"(aa[0]), "r"(aa[1]), "r"(aa[2]), "r"(aa[3]),                 \
          "r"(bb[0]), "r"(bb[1]))

#define CP_ASYNC16(dst, src)                                              \
    asm volatile("cp.async.cg.shared.global [%0], [%1], 16;"              \
                 :: "r"(dst), "l"(src))
#define CP_COMMIT() asm volatile("cp.async.commit_group;")
#define CP_WAIT_ALL() asm volatile("cp.async.wait_group 0;")
#define CP_WAIT1() asm volatile("cp.async.wait_group 1;")

// ===========================================================================
// G1: 128x128 CTA tile, BK=32, 128 threads (4 warps as 2x2, warp tile 64x64).
//   3-stage cp.async pipeline, single __syncthreads per K-iter.
//   A smem [m][k] stride 36; B smem: TRANSB -> [n][k] stride 36,
//   else [k][n] stride 128 XOR-swizzled (col ^ 8*(k&3)).
// MODE: 0 = plain (C=alpha*A@B(+bias)),  1 = QK^T per (b,h)
// ===========================================================================
#define ASTR 36
#define G1_A_TILE (128 * ASTR)        // 4608 floats
#define G1_BT_TILE (128 * ASTR)       // 4608
#define G1_BN_TILE (32 * 128)         // 4096
#define G1_SMEM_T (3 * (G1_A_TILE + G1_BT_TILE))   // 27648 fl = 110592 B
#define G1_SMEM_N (3 * (G1_A_TILE + G1_BN_TILE))   // 26112 fl = 104448 B

template <int TRANSB>
__device__ __forceinline__ void g1_load(
    const float* __restrict__ Abase, const float* __restrict__ Bbase,
    int lda, int ldb, int k0, float* As, float* Bs, int tid)
{
    // A: 128 x 32  (128 threads -> 8 x float4 each)
    {
        const int row = tid >> 3;               // 0..15
        const int col = (tid & 7) * 4;
        const float* src = Abase + (size_t)row * lda + k0 + col;
        unsigned dst = (unsigned)__cvta_generic_to_shared(As + row * ASTR + col);
        #pragma unroll
        for (int r = 0; r < 8; ++r)
            CP_ASYNC16(dst + r * 16 * ASTR * 4, src + (size_t)r * 16 * lda);
    }
    if (TRANSB) {
        const int row = tid >> 3;
        const int col = (tid & 7) * 4;
        const float* src = Bbase + (size_t)row * ldb + k0 + col;
        unsigned dst = (unsigned)__cvta_generic_to_shared(Bs + row * ASTR + col);
        #pragma unroll
        for (int r = 0; r < 8; ++r)
            CP_ASYNC16(dst + r * 16 * ASTR * 4, src + (size_t)r * 16 * ldb);
    } else {
        #pragma unroll
        for (int r = 0; r < 8; ++r) {
            const int elem = r * 128 + tid;
            const int kr = elem >> 5;
            const int c4 = (elem & 31) * 4;
            const float* src = Bbase + (size_t)(k0 + kr) * ldb + c4;
            unsigned dst = (unsigned)__cvta_generic_to_shared(
                Bs + kr * 128 + (c4 ^ (8 * (kr & 3))));
            CP_ASYNC16(dst, src);
        }
    }
}

template <int MODE, int TRANSB>
__global__ __launch_bounds__(128) void gemm_g1_kernel(
    const float* __restrict__ A, const float* __restrict__ B,
    const float* __restrict__ bias, float* __restrict__ C,
    int K, int lda, int ldb, int ldc, float alpha)
{
    extern __shared__ float sm[];
    const int B_TILE = TRANSB ? G1_BT_TILE : G1_BN_TILE;
    float* As = sm;                         // 3 stages
    float* Bs = sm + 3 * G1_A_TILE;         // 3 stages

    const int tid = threadIdx.x;
    const int z = blockIdx.z;

    const float* Ab;
    const float* Bbp;
    float* Cb;
    if (MODE == 0) {
        Ab = A; Bbp = B; Cb = C;
    } else {                              // QK^T per (b,h)
        const int b = z >> 4, h = z & 15;
        Ab  = A + (size_t)b * Ss * QKVN + h * DH;
        Bbp = B + (size_t)b * Ss * QKVN + Ee + h * DH;
        Cb  = C + (size_t)z * Ss * Ss;
    }

    const float* Abase = Ab + (size_t)blockIdx.y * 128 * lda;
    const float* Bbase = TRANSB ? (Bbp + (size_t)blockIdx.x * 128 * ldb)
                                : (Bbp + blockIdx.x * 128);

    const int warp = tid >> 5, lane = tid & 31;
    const int wm = warp >> 1, wn = warp & 1;      // 2x2 warps, warp tile 64x64
    const int g = lane >> 2, t = lane & 3;

    float acc[4][8][4];
    #pragma unroll
    for (int mt = 0; mt < 4; ++mt)
        #pragma unroll
        for (int nt = 0; nt < 8; ++nt)
            #pragma unroll
            for (int r = 0; r < 4; ++r) acc[mt][nt][r] = 0.f;

    const int KT = K >> 5;

    // prologue: stage tiles 0 and 1
    g1_load<TRANSB>(Abase, Bbase, lda, ldb, 0, As, Bs, tid);
    CP_COMMIT();
    if (KT > 1) {
        g1_load<TRANSB>(Abase, Bbase, lda, ldb, 32,
                        As + G1_A_TILE, Bs + B_TILE, tid);
        CP_COMMIT();
    }

    for (int kt = 0; kt < KT; ++kt) {
        if (kt < KT - 1) CP_WAIT1(); else CP_WAIT_ALL();
        __syncthreads();   // also guarantees buffer (kt+2)%3 free (consumed at kt-1)

        if (kt + 2 < KT) {
            const int buf = (kt + 2) % 3;
            g1_load<TRANSB>(Abase, Bbase, lda, ldb, (kt + 2) * 32,
                            As + buf * G1_A_TILE, Bs + buf * B_TILE, tid);
            CP_COMMIT();
        }

        const float* Ac = As + (kt % 3) * G1_A_TILE;
        const float* Bc = Bs + (kt % 3) * B_TILE;

        #pragma unroll
        for (int kk = 0; kk < 32; kk += 8) {
            unsigned a_h[4][4], a_l[4][4];
            const int kcol = kk + t;
            #pragma unroll
            for (int mt = 0; mt < 4; ++mt) {
                const int m0 = wm * 64 + mt * 16 + g;
                split32(Ac[m0 * ASTR + kcol],           a_h[mt][0], a_l[mt][0]);
                split32(Ac[(m0 + 8) * ASTR + kcol],     a_h[mt][1], a_l[mt][1]);
                split32(Ac[m0 * ASTR + kcol + 4],       a_h[mt][2], a_l[mt][2]);
                split32(Ac[(m0 + 8) * ASTR + kcol + 4], a_h[mt][3], a_l[mt][3]);
            }
            #pragma unroll
            for (int nt = 0; nt < 8; ++nt) {
                const int n0 = wn * 64 + nt * 8 + g;
                float y0, y1;
                if (TRANSB) {
                    y0 = Bc[n0 * ASTR + kk + t];
                    y1 = Bc[n0 * ASTR + kk + t + 4];
                } else {
                    const int nsw = n0 ^ (8 * t);
                    y0 = Bc[(kk + t) * 128 + nsw];
                    y1 = Bc[(kk + t + 4) * 128 + nsw];
                }
                unsigned b_h[2], b_l[2];
                split32(y0, b_h[0], b_l[0]);
                split32(y1, b_h[1], b_l[1]);
                #pragma unroll
                for (int mt = 0; mt < 4; ++mt) {
                    MMA_TF32(acc[mt][nt], a_h[mt], b_h);
                    MMA_TF32(acc[mt][nt], a_h[mt], b_l);
                    MMA_TF32(acc[mt][nt], a_l[mt], b_h);
                }
            }
        }
    }

    // epilogue
    #pragma unroll
    for (int mt = 0; mt < 4; ++mt) {
        #pragma unroll
        for (int nt = 0; nt < 8; ++nt) {
            const int row0 = blockIdx.y * 128 + wm * 64 + mt * 16 + g;
            const int col  = blockIdx.x * 128 + wn * 64 + nt * 8 + t * 2;
            float bv0 = 0.f, bv1 = 0.f;
            if (bias) { bv0 = bias[col]; bv1 = bias[col + 1]; }
            float2 v0 = make_float2(acc[mt][nt][0] * alpha + bv0,
                                    acc[mt][nt][1] * alpha + bv1);
            *(float2*)(Cb + (size_t)row0 * ldc + col) = v0;
            float2 v1 = make_float2(acc[mt][nt][2] * alpha + bv0,
                                    acc[mt][nt][3] * alpha + bv1);
            *(float2*)(Cb + (size_t)(row0 + 8) * ldc + col) = v1;
        }
    }
}

// ---------------------------------------------------------------------------
// Fused softmax + threshold mask + renorm (in place) + sparse nnz extraction.
// ---------------------------------------------------------------------------
__global__ __launch_bounds__(256) void softmax_mask_kernel(
    float* __restrict__ P, int* __restrict__ scnt,
    int* __restrict__ sidx, float* __restrict__ sval)
{
    const int row = blockIdx.x;
    float* Pr = P + (size_t)row * Ss;
    const int tid = threadIdx.x;
    const int lane = tid & 31, wid = tid >> 5;

    __shared__ float sv[8];
    __shared__ int   si[8];
    __shared__ int   cnt;
    if (tid == 0) cnt = 0;

    float4 lv = ((const float4*)Pr)[tid];
    float l[4] = {lv.x, lv.y, lv.z, lv.w};

    float m = l[0]; int mi = 4 * tid;
    #pragma unroll
    for (int r = 1; r < 4; ++r)
        if (l[r] > m) { m = l[r]; mi = 4 * tid + r; }
    #pragma unroll
    for (int o = 16; o > 0; o >>= 1) {
        float ov = __shfl_down_sync(0xffffffffu, m, o);
        int   oi = __shfl_down_sync(0xffffffffu, mi, o);
        if (ov > m || (ov == m && oi < mi)) { m = ov; mi = oi; }
    }
    if (lane == 0) { sv[wid] = m; si[wid] = mi; }
    __syncthreads();
    if (wid == 0) {
        float v = (lane < 8) ? sv[lane] : -3.4e38f;
        int vi  = (lane < 8) ? si[lane] : 0x7fffffff;
        #pragma unroll
        for (int o = 4; o > 0; o >>= 1) {
            float ov = __shfl_down_sync(0xffffffffu, v, o);
            int   oi = __shfl_down_sync(0xffffffffu, vi, o);
            if (ov > v || (ov == v && oi < vi)) { v = ov; vi = oi; }
        }
        if (lane == 0) { sv[0] = v; si[0] = vi; }
    }
    __syncthreads();
    const float rowmax = sv[0];
    const int argmax = si[0];
    __syncthreads();

    float e[4]; float zsum = 0.f;
    #pragma unroll
    for (int r = 0; r < 4; ++r) { e[r] = expf(l[r] - rowmax); zsum += e[r]; }
    #pragma unroll
    for (int o = 16; o > 0; o >>= 1) zsum += __shfl_xor_sync(0xffffffffu, zsum, o);
    if (lane == 0) sv[wid] = zsum;
    __syncthreads();
    float Z = 0.f;
    #pragma unroll
    for (int w = 0; w < 8; ++w) Z += sv[w];
    __syncthreads();

    const float invZ = 1.0f / Z;
    float p[4]; float msum = 0.f;
    #pragma unroll
    for (int r = 0; r < 4; ++r) {
        p[r] = e[r] * invZ;
        if (p[r] > 0.1f) msum += p[r];
    }
    #pragma unroll
    for (int o = 16; o > 0; o >>= 1) msum += __shfl_xor_sync(0xffffffffu, msum, o);
    if (lane == 0) sv[wid] = msum;
    __syncthreads();
    float sumMask = 0.f;
    #pragma unroll
    for (int w = 0; w < 8; ++w) sumMask += sv[w];

    float4 ov;
    if (sumMask > 0.f) {
        const float inv = 1.0f / sumMask;
        float q[4];
        #pragma unroll
        for (int r = 0; r < 4; ++r)
            q[r] = (p[r] > 0.1f) ? p[r] * inv : 0.f;
        ov.x = q[0]; ov.y = q[1]; ov.z = q[2]; ov.w = q[3];
        #pragma unroll
        for (int r = 0; r < 4; ++r) {
            if (p[r] > 0.1f) {
                int pos = atomicAdd(&cnt, 1);
                if (pos < NNZ_CAP) {
                    sidx[(size_t)row * NNZ_CAP + pos] = 4 * tid + r;
                    sval[(size_t)row * NNZ_CAP + pos] = q[r];
                }
            }
        }
    } else {
        ov.x = (4 * tid + 0 == argmax) ? 1.f : 0.f;
        ov.y = (4 * tid + 1 == argmax) ? 1.f : 0.f;
        ov.z = (4 * tid + 2 == argmax) ? 1.f : 0.f;
        ov.w = (4 * tid + 3 == argmax) ? 1.f : 0.f;
        if (argmax >= 4 * tid && argmax < 4 * tid + 4) {
            int pos = atomicAdd(&cnt, 1);
            if (pos < NNZ_CAP) {
                sidx[(size_t)row * NNZ_CAP + pos] = argmax;
                sval[(size_t)row * NNZ_CAP + pos] = 1.0f;
            }
        }
    }
    ((float4*)Pr)[tid] = ov;

    __syncthreads();
    if (tid == 0) scnt[row] = (cnt < NNZ_CAP) ? cnt : NNZ_CAP;
}

// ---------------------------------------------------------------------------
// Sparse AV: one warp per attention row. out[i,:] = sum_k val_k * V[idx_k,:]
// ---------------------------------------------------------------------------
__global__ __launch_bounds__(256) void av_sparse_kernel(
    const int* __restrict__ scnt, const int* __restrict__ sidx,
    const float* __restrict__ sval, const float* __restrict__ qkv,
    float* __restrict__ ao)
{
    const int r = blockIdx.x * 8 + (threadIdx.x >> 5);
    const int lane = threadIdx.x & 31;

    const int bh = r >> 10, i = r & 1023;
    const int b = bh >> 4, h = bh & 15;
    const float* Vb = qkv + (size_t)b * Ss * QKVN + 2 * Ee + h * DH;

    const int c = scnt[r];
    float a0 = 0.f, a1 = 0.f;
    for (int k = 0; k < c; ++k) {
        const int j = sidx[(size_t)r * NNZ_CAP + k];
        const float v = sval[(size_t)r * NNZ_CAP + k];
        const float* Vr = Vb + (size_t)j * QKVN;
        a0 += v * Vr[lane];
        a1 += v * Vr[lane + 32];
    }
    float* Or = ao + (size_t)(b * Ss + i) * Ee + h * DH;
    Or[lane] = a0;
    Or[lane + 32] = a1;
}

// ---------------------------------------------------------------------------
// Launch
// ---------------------------------------------------------------------------
static float* sym_addr(const void* sym)
{
    void* p = nullptr;
    cudaGetSymbolAddress(&p, sym);
    return (float*)p;
}

extern "C" void kernel_launch(void* const* d_in, const int* in_sizes, int n_in,
                              void* d_out, int out_size)
{
    const float* x      = (const float*)d_in[0];
    const float* w_qkv  = (const float*)d_in[1];
    const float* b_qkv  = (const float*)d_in[2];
    const float* w_proj = (const float*)d_in[3];
    const float* b_proj = (const float*)d_in[4];

    float* qkv = sym_addr(g_qkv);
    float* ao  = sym_addr(g_ao);
    int*   scnt = (int*)sym_addr(g_scnt);
    int*   sidx = (int*)sym_addr(g_sidx);
    float* sval = sym_addr(g_sval);

    const size_t OUT_N  = (size_t)Bb * Ss * Ee;
    const size_t ATTN_N = (size_t)Bb * Hh * Ss * Ss;

    float* out = (float*)d_out;
    float* P;
    float* mainOut;
    if ((size_t)out_size >= OUT_N + ATTN_N) {
        mainOut = out;
        P = out + OUT_N;
    } else if ((size_t)out_size == ATTN_N) {
        mainOut = sym_addr(g_spill);
        P = out;
    } else {
        mainOut = out;
        P = sym_addr(g_P);
    }

    const int smemN = G1_SMEM_N * sizeof(float);   // 104448
    const int smemT = G1_SMEM_T * sizeof(float);   // 110592
    cudaFuncSetAttribute(gemm_g1_kernel<0, 0>,
                         cudaFuncAttributeMaxDynamicSharedMemorySize, smemN);
    cudaFuncSetAttribute(gemm_g1_kernel<1, 1>,
                         cudaFuncAttributeMaxDynamicSharedMemorySize, smemT);

    // 1. QKV projection: [4096,1024] @ [1024,3072] + bias
    {
        dim3 grid(QKVN / 128, MROWS / 128, 1);
        gemm_g1_kernel<0, 0><<<grid, 128, smemN>>>(
            x, w_qkv, b_qkv, qkv, Ee, Ee, QKVN, QKVN, 1.0f);
    }
    // 2. QK^T logits per (b,h), alpha = Dh^-0.5
    {
        dim3 grid(Ss / 128, Ss / 128, Bb * Hh);
        gemm_g1_kernel<1, 1><<<grid, 128, smemT>>>(
            qkv, qkv, nullptr, P, DH, QKVN, QKVN, Ss, 0.125f);
    }
    // 3. fused softmax + threshold mask + renorm + sparse extraction
    softmax_mask_kernel<<<NROWS, 256>>>(P, scnt, sidx, sval);
    // 4. sparse AV (<= 9 nnz per row guaranteed)
    av_sparse_kernel<<<NROWS / 8, 256>>>(scnt, sidx, sval, qkv, ao);
    // 5. output projection: [4096,1024] @ [1024,1024] + bias
    {
        dim3 grid(Ee / 128, MROWS / 128, 1);
        gemm_g1_kernel<0, 0><<<grid, 128, smemN>>>(
            ao, w_proj, b_proj, mainOut, Ee, Ee, Ee, Ee, 1.0f);
    }
}

// round 7
// speedup vs baseline: 2.4069x; 1.1383x over previous
#include <cuda_runtime.h>
#include <math.h>

// Problem constants
#define Bb 4
#define Ss 1024
#define Ee 1024
#define Hh 16
#define DH 64
#define MROWS (Bb * Ss)      // 4096
#define QKVN (3 * Ee)        // 3072
#define NROWS (Bb * Hh * Ss) // 65536 attention rows
#define NNZ_CAP 16

// Scratch
__device__ float g_qkv[(size_t)MROWS * QKVN];
__device__ float g_P[(size_t)Bb * Hh * Ss * Ss];
__device__ float g_ao[(size_t)MROWS * Ee];
__device__ float g_spill[(size_t)MROWS * Ee];
__device__ int   g_scnt[NROWS];
__device__ int   g_sidx[(size_t)NROWS * NNZ_CAP];
__device__ float g_sval[(size_t)NROWS * NNZ_CAP];

// ---------------------------------------------------------------------------
// Common helpers
// ---------------------------------------------------------------------------
__device__ __forceinline__ unsigned f2tf32_rna(float x) {
    unsigned u;
    asm("cvt.rna.tf32.f32 %0, %1;" : "=r"(u) : "f"(x));
    return u;
}

template <int PASSES>
__device__ __forceinline__ void splitP(float x, unsigned& h, unsigned& l) {
    if (PASSES == 1) {
        h = f2tf32_rna(x);            // single pass: round-to-nearest tf32
        l = 0u;
    } else {
        unsigned hu = __float_as_uint(x) & 0xffffe000u;  // truncate
        h = hu;
        l = __float_as_uint(x - __uint_as_float(hu));    // residual
    }
}

#define MMA_TF32(cc, aa, bb)                                              \
    asm volatile(                                                          \
        "mma.sync.aligned.m16n8k8.row.col.f32.tf32.tf32.f32 "             \
        "{%0,%1,%2,%3}, {%4,%5,%6,%7}, {%8,%9}, {%0,%1,%2,%3};"           \
        : "+f"(cc[0]), "+f"(cc[1]), "+f"(cc[2]), "+f"(cc[3])              \
        : "r"(aa[0]), "r"(aa[1]), "r"(aa[2]), "r"(aa[3]),                 \
          "r"(bb[0]), "r"(bb[1]))

#define CP_ASYNC16(dst, src)                                              \
    asm volatile("cp.async.cg.shared.global [%0], [%1], 16;"              \
                 :: "r"(dst), "l"(src))
#define CP_COMMIT() asm volatile("cp.async.commit_group;")
#define CP_WAIT_ALL() asm volatile("cp.async.wait_group 0;")
#define CP_WAIT1() asm volatile("cp.async.wait_group 1;")

// ===========================================================================
// G1: 128x128 CTA tile, BK=32, 128 threads (4 warps as 2x2, warp tile 64x64).
//   3-stage cp.async pipeline, single __syncthreads per K-iter.
//   PASSES: 3 = full tf32x3 (fp32-accurate), 2 = hi*hi+hi*lo, 1 = plain tf32.
// MODE: 0 = plain (C=alpha*A@B(+bias)),  1 = QK^T per (b,h)
// ===========================================================================
#define ASTR 36
#define G1_A_TILE (128 * ASTR)        // 4608 floats
#define G1_BT_TILE (128 * ASTR)       // 4608
#define G1_BN_TILE (32 * 128)         // 4096
#define G1_SMEM_T (3 * (G1_A_TILE + G1_BT_TILE))   // 110592 B
#define G1_SMEM_N (3 * (G1_A_TILE + G1_BN_TILE))   // 104448 B

template <int TRANSB>
__device__ __forceinline__ void g1_load(
    const float* __restrict__ Abase, const float* __restrict__ Bbase,
    int lda, int ldb, int k0, float* As, float* Bs, int tid)
{
    // A: 128 x 32  (128 threads -> 8 x float4 each)
    {
        const int row = tid >> 3;               // 0..15
        const int col = (tid & 7) * 4;
        const float* src = Abase + (size_t)row * lda + k0 + col;
        unsigned dst = (unsigned)__cvta_generic_to_shared(As + row * ASTR + col);
        #pragma unroll
        for (int r = 0; r < 8; ++r)
            CP_ASYNC16(dst + r * 16 * ASTR * 4, src + (size_t)r * 16 * lda);
    }
    if (TRANSB) {
        const int row = tid >> 3;
        const int col = (tid & 7) * 4;
        const float* src = Bbase + (size_t)row * ldb + k0 + col;
        unsigned dst = (unsigned)__cvta_generic_to_shared(Bs + row * ASTR + col);
        #pragma unroll
        for (int r = 0; r < 8; ++r)
            CP_ASYNC16(dst + r * 16 * ASTR * 4, src + (size_t)r * 16 * ldb);
    } else {
        #pragma unroll
        for (int r = 0; r < 8; ++r) {
            const int elem = r * 128 + tid;
            const int kr = elem >> 5;
            const int c4 = (elem & 31) * 4;
            const float* src = Bbase + (size_t)(k0 + kr) * ldb + c4;
            unsigned dst = (unsigned)__cvta_generic_to_shared(
                Bs + kr * 128 + (c4 ^ (8 * (kr & 3))));
            CP_ASYNC16(dst, src);
        }
    }
}

template <int MODE, int TRANSB, int PASSES>
__global__ __launch_bounds__(128) void gemm_g1_kernel(
    const float* __restrict__ A, const float* __restrict__ B,
    const float* __restrict__ bias, float* __restrict__ C,
    int K, int lda, int ldb, int ldc, float alpha)
{
    extern __shared__ float sm[];
    const int B_TILE = TRANSB ? G1_BT_TILE : G1_BN_TILE;
    float* As = sm;                         // 3 stages
    float* Bs = sm + 3 * G1_A_TILE;         // 3 stages

    const int tid = threadIdx.x;
    const int z = blockIdx.z;

    const float* Ab;
    const float* Bbp;
    float* Cb;
    if (MODE == 0) {
        Ab = A; Bbp = B; Cb = C;
    } else {                              // QK^T per (b,h)
        const int b = z >> 4, h = z & 15;
        Ab  = A + (size_t)b * Ss * QKVN + h * DH;
        Bbp = B + (size_t)b * Ss * QKVN + Ee + h * DH;
        Cb  = C + (size_t)z * Ss * Ss;
    }

    const float* Abase = Ab + (size_t)blockIdx.y * 128 * lda;
    const float* Bbase = TRANSB ? (Bbp + (size_t)blockIdx.x * 128 * ldb)
                                : (Bbp + blockIdx.x * 128);

    const int warp = tid >> 5, lane = tid & 31;
    const int wm = warp >> 1, wn = warp & 1;      // 2x2 warps, warp tile 64x64
    const int g = lane >> 2, t = lane & 3;

    float acc[4][8][4];
    #pragma unroll
    for (int mt = 0; mt < 4; ++mt)
        #pragma unroll
        for (int nt = 0; nt < 8; ++nt)
            #pragma unroll
            for (int r = 0; r < 4; ++r) acc[mt][nt][r] = 0.f;

    const int KT = K >> 5;

    g1_load<TRANSB>(Abase, Bbase, lda, ldb, 0, As, Bs, tid);
    CP_COMMIT();
    if (KT > 1) {
        g1_load<TRANSB>(Abase, Bbase, lda, ldb, 32,
                        As + G1_A_TILE, Bs + B_TILE, tid);
        CP_COMMIT();
    }

    for (int kt = 0; kt < KT; ++kt) {
        if (kt < KT - 1) CP_WAIT1(); else CP_WAIT_ALL();
        __syncthreads();

        if (kt + 2 < KT) {
            const int buf = (kt + 2) % 3;
            g1_load<TRANSB>(Abase, Bbase, lda, ldb, (kt + 2) * 32,
                            As + buf * G1_A_TILE, Bs + buf * B_TILE, tid);
            CP_COMMIT();
        }

        const float* Ac = As + (kt % 3) * G1_A_TILE;
        const float* Bc = Bs + (kt % 3) * B_TILE;

        #pragma unroll
        for (int kk = 0; kk < 32; kk += 8) {
            unsigned a_h[4][4], a_l[4][4];
            const int kcol = kk + t;
            #pragma unroll
            for (int mt = 0; mt < 4; ++mt) {
                const int m0 = wm * 64 + mt * 16 + g;
                splitP<PASSES>(Ac[m0 * ASTR + kcol],           a_h[mt][0], a_l[mt][0]);
                splitP<PASSES>(Ac[(m0 + 8) * ASTR + kcol],     a_h[mt][1], a_l[mt][1]);
                splitP<PASSES>(Ac[m0 * ASTR + kcol + 4],       a_h[mt][2], a_l[mt][2]);
                splitP<PASSES>(Ac[(m0 + 8) * ASTR + kcol + 4], a_h[mt][3], a_l[mt][3]);
            }
            #pragma unroll
            for (int nt = 0; nt < 8; ++nt) {
                const int n0 = wn * 64 + nt * 8 + g;
                float y0, y1;
                if (TRANSB) {
                    y0 = Bc[n0 * ASTR + kk + t];
                    y1 = Bc[n0 * ASTR + kk + t + 4];
                } else {
                    const int nsw = n0 ^ (8 * t);
                    y0 = Bc[(kk + t) * 128 + nsw];
                    y1 = Bc[(kk + t + 4) * 128 + nsw];
                }
                unsigned b_h[2], b_l[2];
                splitP<PASSES>(y0, b_h[0], b_l[0]);
                splitP<PASSES>(y1, b_h[1], b_l[1]);
                #pragma unroll
                for (int mt = 0; mt < 4; ++mt) {
                    MMA_TF32(acc[mt][nt], a_h[mt], b_h);
                    if (PASSES >= 2) MMA_TF32(acc[mt][nt], a_h[mt], b_l);
                    if (PASSES >= 3) MMA_TF32(acc[mt][nt], a_l[mt], b_h);
                }
            }
        }
    }

    // epilogue
    #pragma unroll
    for (int mt = 0; mt < 4; ++mt) {
        #pragma unroll
        for (int nt = 0; nt < 8; ++nt) {
            const int row0 = blockIdx.y * 128 + wm * 64 + mt * 16 + g;
            const int col  = blockIdx.x * 128 + wn * 64 + nt * 8 + t * 2;
            float bv0 = 0.f, bv1 = 0.f;
            if (bias) { bv0 = bias[col]; bv1 = bias[col + 1]; }
            float2 v0 = make_float2(acc[mt][nt][0] * alpha + bv0,
                                    acc[mt][nt][1] * alpha + bv1);
            *(float2*)(Cb + (size_t)row0 * ldc + col) = v0;
            float2 v1 = make_float2(acc[mt][nt][2] * alpha + bv0,
                                    acc[mt][nt][3] * alpha + bv1);
            *(float2*)(Cb + (size_t)(row0 + 8) * ldc + col) = v1;
        }
    }
}

// ---------------------------------------------------------------------------
// Fused softmax + threshold mask + renorm (in place) + sparse nnz extraction.
// ---------------------------------------------------------------------------
__global__ __launch_bounds__(256) void softmax_mask_kernel(
    float* __restrict__ P, int* __restrict__ scnt,
    int* __restrict__ sidx, float* __restrict__ sval)
{
    const int row = blockIdx.x;
    float* Pr = P + (size_t)row * Ss;
    const int tid = threadIdx.x;
    const int lane = tid & 31, wid = tid >> 5;

    __shared__ float sv[8];
    __shared__ int   si[8];
    __shared__ int   cnt;
    if (tid == 0) cnt = 0;

    float4 lv = ((const float4*)Pr)[tid];
    float l[4] = {lv.x, lv.y, lv.z, lv.w};

    float m = l[0]; int mi = 4 * tid;
    #pragma unroll
    for (int r = 1; r < 4; ++r)
        if (l[r] > m) { m = l[r]; mi = 4 * tid + r; }
    #pragma unroll
    for (int o = 16; o > 0; o >>= 1) {
        float ov = __shfl_down_sync(0xffffffffu, m, o);
        int   oi = __shfl_down_sync(0xffffffffu, mi, o);
        if (ov > m || (ov == m && oi < mi)) { m = ov; mi = oi; }
    }
    if (lane == 0) { sv[wid] = m; si[wid] = mi; }
    __syncthreads();
    if (wid == 0) {
        float v = (lane < 8) ? sv[lane] : -3.4e38f;
        int vi  = (lane < 8) ? si[lane] : 0x7fffffff;
        #pragma unroll
        for (int o = 4; o > 0; o >>= 1) {
            float ov = __shfl_down_sync(0xffffffffu, v, o);
            int   oi = __shfl_down_sync(0xffffffffu, vi, o);
            if (ov > v || (ov == v && oi < vi)) { v = ov; vi = oi; }
        }
        if (lane == 0) { sv[0] = v; si[0] = vi; }
    }
    __syncthreads();
    const float rowmax = sv[0];
    const int argmax = si[0];
    __syncthreads();

    float e[4]; float zsum = 0.f;
    #pragma unroll
    for (int r = 0; r < 4; ++r) { e[r] = expf(l[r] - rowmax); zsum += e[r]; }
    #pragma unroll
    for (int o = 16; o > 0; o >>= 1) zsum += __shfl_xor_sync(0xffffffffu, zsum, o);
    if (lane == 0) sv[wid] = zsum;
    __syncthreads();
    float Z = 0.f;
    #pragma unroll
    for (int w = 0; w < 8; ++w) Z += sv[w];
    __syncthreads();

    const float invZ = 1.0f / Z;
    float p[4]; float msum = 0.f;
    #pragma unroll
    for (int r = 0; r < 4; ++r) {
        p[r] = e[r] * invZ;
        if (p[r] > 0.1f) msum += p[r];
    }
    #pragma unroll
    for (int o = 16; o > 0; o >>= 1) msum += __shfl_xor_sync(0xffffffffu, msum, o);
    if (lane == 0) sv[wid] = msum;
    __syncthreads();
    float sumMask = 0.f;
    #pragma unroll
    for (int w = 0; w < 8; ++w) sumMask += sv[w];

    float4 ov;
    if (sumMask > 0.f) {
        const float inv = 1.0f / sumMask;
        float q[4];
        #pragma unroll
        for (int r = 0; r < 4; ++r)
            q[r] = (p[r] > 0.1f) ? p[r] * inv : 0.f;
        ov.x = q[0]; ov.y = q[1]; ov.z = q[2]; ov.w = q[3];
        #pragma unroll
        for (int r = 0; r < 4; ++r) {
            if (p[r] > 0.1f) {
                int pos = atomicAdd(&cnt, 1);
                if (pos < NNZ_CAP) {
                    sidx[(size_t)row * NNZ_CAP + pos] = 4 * tid + r;
                    sval[(size_t)row * NNZ_CAP + pos] = q[r];
                }
            }
        }
    } else {
        ov.x = (4 * tid + 0 == argmax) ? 1.f : 0.f;
        ov.y = (4 * tid + 1 == argmax) ? 1.f : 0.f;
        ov.z = (4 * tid + 2 == argmax) ? 1.f : 0.f;
        ov.w = (4 * tid + 3 == argmax) ? 1.f : 0.f;
        if (argmax >= 4 * tid && argmax < 4 * tid + 4) {
            int pos = atomicAdd(&cnt, 1);
            if (pos < NNZ_CAP) {
                sidx[(size_t)row * NNZ_CAP + pos] = argmax;
                sval[(size_t)row * NNZ_CAP + pos] = 1.0f;
            }
        }
    }
    ((float4*)Pr)[tid] = ov;

    __syncthreads();
    if (tid == 0) scnt[row] = (cnt < NNZ_CAP) ? cnt : NNZ_CAP;
}

// ---------------------------------------------------------------------------
// Sparse AV: one warp per attention row. out[i,:] = sum_k val_k * V[idx_k,:]
// ---------------------------------------------------------------------------
__global__ __launch_bounds__(256) void av_sparse_kernel(
    const int* __restrict__ scnt, const int* __restrict__ sidx,
    const float* __restrict__ sval, const float* __restrict__ qkv,
    float* __restrict__ ao)
{
    const int r = blockIdx.x * 8 + (threadIdx.x >> 5);
    const int lane = threadIdx.x & 31;

    const int bh = r >> 10, i = r & 1023;
    const int b = bh >> 4, h = bh & 15;
    const float* Vb = qkv + (size_t)b * Ss * QKVN + 2 * Ee + h * DH;

    const int c = scnt[r];
    float a0 = 0.f, a1 = 0.f;
    for (int k = 0; k < c; ++k) {
        const int j = sidx[(size_t)r * NNZ_CAP + k];
        const float v = sval[(size_t)r * NNZ_CAP + k];
        const float* Vr = Vb + (size_t)j * QKVN;
        a0 += v * Vr[lane];
        a1 += v * Vr[lane + 32];
    }
    float* Or = ao + (size_t)(b * Ss + i) * Ee + h * DH;
    Or[lane] = a0;
    Or[lane + 32] = a1;
}

// ---------------------------------------------------------------------------
// Launch
// ---------------------------------------------------------------------------
static float* sym_addr(const void* sym)
{
    void* p = nullptr;
    cudaGetSymbolAddress(&p, sym);
    return (float*)p;
}

extern "C" void kernel_launch(void* const* d_in, const int* in_sizes, int n_in,
                              void* d_out, int out_size)
{
    const float* x      = (const float*)d_in[0];
    const float* w_qkv  = (const float*)d_in[1];
    const float* b_qkv  = (const float*)d_in[2];
    const float* w_proj = (const float*)d_in[3];
    const float* b_proj = (const float*)d_in[4];

    float* qkv = sym_addr(g_qkv);
    float* ao  = sym_addr(g_ao);
    int*   scnt = (int*)sym_addr(g_scnt);
    int*   sidx = (int*)sym_addr(g_sidx);
    float* sval = sym_addr(g_sval);

    const size_t OUT_N  = (size_t)Bb * Ss * Ee;
    const size_t ATTN_N = (size_t)Bb * Hh * Ss * Ss;

    float* out = (float*)d_out;
    float* P;
    float* mainOut;
    if ((size_t)out_size >= OUT_N + ATTN_N) {
        mainOut = out;
        P = out + OUT_N;
    } else if ((size_t)out_size == ATTN_N) {
        mainOut = sym_addr(g_spill);
        P = out;
    } else {
        mainOut = out;
        P = sym_addr(g_P);
    }

    const int smemN = G1_SMEM_N * sizeof(float);   // 104448
    const int smemT = G1_SMEM_T * sizeof(float);   // 110592
    cudaFuncSetAttribute(gemm_g1_kernel<0, 0, 3>,
                         cudaFuncAttributeMaxDynamicSharedMemorySize, smemN);
    cudaFuncSetAttribute(gemm_g1_kernel<0, 0, 2>,
                         cudaFuncAttributeMaxDynamicSharedMemorySize, smemN);
    cudaFuncSetAttribute(gemm_g1_kernel<0, 0, 1>,
                         cudaFuncAttributeMaxDynamicSharedMemorySize, smemN);
    cudaFuncSetAttribute(gemm_g1_kernel<1, 1, 3>,
                         cudaFuncAttributeMaxDynamicSharedMemorySize, smemT);

    // 1a. Q,K projection: [4096,1024] @ [1024,2048] + bias  (tf32x3 — feeds mask)
    {
        dim3 grid(2048 / 128, MROWS / 128, 1);
        gemm_g1_kernel<0, 0, 3><<<grid, 128, smemN>>>(
            x, w_qkv, b_qkv, qkv, Ee, Ee, QKVN, QKVN, 1.0f);
    }
    // 1b. V projection: [4096,1024] @ [1024,1024] + bias  (tf32x1 — output only)
    {
        dim3 grid(1024 / 128, MROWS / 128, 1);
        gemm_g1_kernel<0, 0, 1><<<grid, 128, smemN>>>(
            x, w_qkv + 2048, b_qkv + 2048, qkv + 2048, Ee, Ee, QKVN, QKVN, 1.0f);
    }
    // 2. QK^T logits per (b,h), alpha = Dh^-0.5  (tf32x3)
    {
        dim3 grid(Ss / 128, Ss / 128, Bb * Hh);
        gemm_g1_kernel<1, 1, 3><<<grid, 128, smemT>>>(
            qkv, qkv, nullptr, P, DH, QKVN, QKVN, Ss, 0.125f);
    }
    // 3. fused softmax + threshold mask + renorm + sparse extraction
    softmax_mask_kernel<<<NROWS, 256>>>(P, scnt, sidx, sval);
    // 4. sparse AV (<= 9 nnz per row guaranteed)
    av_sparse_kernel<<<NROWS / 8, 256>>>(scnt, sidx, sval, qkv, ao);
    // 5. output projection: [4096,1024] @ [1024,1024] + bias  (tf32x2)
    {
        dim3 grid(Ee / 128, MROWS / 128, 1);
        gemm_g1_kernel<0, 0, 2><<<grid, 128, smemN>>>(
            ao, w_proj, b_proj, mainOut, Ee, Ee, Ee, Ee, 1.0f);
    }
}